// round 5
// baseline (speedup 1.0000x reference)
#include <cuda_runtime.h>
#include <cuda_bf16.h>
#include <math.h>
#include <stdint.h>

// Problem constants
#define BATCH 2
#define DIM   256
#define HW    64
#define LSEQ  4096          // 64*64
#define BL    8192          // BATCH*LSEQ
#define DI    512           // d_inner
#define NST   16            // d_state
#define RNK   16            // dt_rank
#define XZW   1024          // 2*DI
#define HIDW  1024          // 4*DIM

// ---------------- scratch (static device globals; no allocation) -------------
__device__ float g_yn  [(size_t)BL * DIM];   // layernorm output (B,L,C)
__device__ float g_xz  [(size_t)BL * XZW];   // xz projection (xm | z)
__device__ float g_u   [(size_t)BL * DI];    // conv+silu output
__device__ float g_proj[(size_t)BL * 48];    // dt_raw(16) | B(16) | C(16)
__device__ float g_dt  [(size_t)BL * DI];    // softplus dt
__device__ float g_ym  [(size_t)BL * DI];    // scan output ys, then gated ym
__device__ float g_y2  [(size_t)BL * DIM];
__device__ float g_hid [(size_t)BL * HIDW];
__device__ float g_y3  [(size_t)BL * DIM];

// ---------------- transpose: in (B, D1, D2) -> out (B, D2, D1) ---------------
__global__ void k_transpose(const float* __restrict__ in, float* __restrict__ out,
                            int D1, int D2) {
    __shared__ float tile[32][33];
    int b  = blockIdx.z;
    int i0 = blockIdx.y * 32;   // along D1
    int j0 = blockIdx.x * 32;   // along D2
    int tx = threadIdx.x, ty = threadIdx.y;
    const float* ip = in  + (size_t)b * D1 * D2;
    float*       op = out + (size_t)b * D1 * D2;
#pragma unroll
    for (int s = 0; s < 32; s += 8)
        tile[ty + s][tx] = ip[(size_t)(i0 + ty + s) * D2 + j0 + tx];
    __syncthreads();
#pragma unroll
    for (int s = 0; s < 32; s += 8)
        op[(size_t)(j0 + ty + s) * D1 + i0 + tx] = tile[tx][ty + s];
}

// ---------------- layernorm (in place on (BL, 256) rows), warp per row -------
__global__ void k_layernorm(float* __restrict__ y,
                            const float* __restrict__ gamma,
                            const float* __restrict__ beta) {
    int gw   = (blockIdx.x * blockDim.x + threadIdx.x) >> 5;
    int lane = threadIdx.x & 31;
    if (gw >= BL) return;
    float* row = y + (size_t)gw * DIM;
    float v[8];
    float s = 0.f;
#pragma unroll
    for (int t = 0; t < 8; t++) { v[t] = row[lane + 32 * t]; s += v[t]; }
#pragma unroll
    for (int o = 16; o > 0; o >>= 1) s += __shfl_xor_sync(~0u, s, o);
    float mu = s * (1.f / DIM);
    float var = 0.f;
#pragma unroll
    for (int t = 0; t < 8; t++) { float d = v[t] - mu; var += d * d; }
#pragma unroll
    for (int o = 16; o > 0; o >>= 1) var += __shfl_xor_sync(~0u, var, o);
    float rstd = rsqrtf(var * (1.f / DIM) + 1e-5f);
#pragma unroll
    for (int t = 0; t < 8; t++) {
        int c = lane + 32 * t;
        row[c] = (v[t] - mu) * rstd * gamma[c] + beta[c];
    }
}

// ---------------- causal depthwise conv(4) + silu, 4 channels/thread ---------
__global__ void k_conv_silu(const float* __restrict__ xz,
                            const float* __restrict__ cw,
                            const float* __restrict__ cb,
                            float* __restrict__ u) {
    int t = blockIdx.x * blockDim.x + threadIdx.x;
    if (t >= BL * DI / 4) return;
    int d4   = (t & (DI / 4 - 1)) * 4;
    int lrow = t >> 7;              // (b*L + l)
    int l    = lrow & (LSEQ - 1);
    float4 acc = *(const float4*)(cb + d4);
#pragma unroll
    for (int k = 0; k < 4; k++) {
        int ll = l - 3 + k;
        if (ll >= 0) {
            float4 xv = *(const float4*)(xz + (size_t)(lrow - 3 + k) * XZW + d4);
            acc.x += cw[(d4 + 0) * 4 + k] * xv.x;
            acc.y += cw[(d4 + 1) * 4 + k] * xv.y;
            acc.z += cw[(d4 + 2) * 4 + k] * xv.z;
            acc.w += cw[(d4 + 3) * 4 + k] * xv.w;
        }
    }
    float4 o;
    o.x = acc.x / (1.f + __expf(-acc.x));
    o.y = acc.y / (1.f + __expf(-acc.y));
    o.z = acc.z / (1.f + __expf(-acc.z));
    o.w = acc.w / (1.f + __expf(-acc.w));
    *(float4*)(u + (size_t)t * 4) = o;
}

// ---------------- x-proj: proj(BL,48) = u(BL,512) @ W_xp(48,512)^T ----------
__global__ void k_proj(const float* __restrict__ u,
                       const float* __restrict__ Wxp,
                       float* __restrict__ proj) {
    int gw   = (blockIdx.x * blockDim.x + threadIdx.x) >> 5;
    int lane = threadIdx.x & 31;
    if (gw >= BL) return;
    const float* ur = u + (size_t)gw * DI;
    float ureg[16];
#pragma unroll
    for (int t = 0; t < 16; t++) ureg[t] = ur[lane + 32 * t];
    for (int j = 0; j < 48; j++) {
        const float* w = Wxp + (size_t)j * DI;
        float s = 0.f;
#pragma unroll
        for (int t = 0; t < 16; t++) s += ureg[t] * w[lane + 32 * t];
#pragma unroll
        for (int o = 16; o > 0; o >>= 1) s += __shfl_xor_sync(~0u, s, o);
        if (lane == 0) proj[(size_t)gw * 48 + j] = s;
    }
}

// ---------------- dt = softplus(proj[:, :16] @ W_dt^T + b_dt) ----------------
__global__ void k_dt(const float* __restrict__ proj,
                     const float* __restrict__ Wdt,
                     const float* __restrict__ bdt,
                     float* __restrict__ dt) {
    __shared__ float p[16];
    int i = blockIdx.x;
    int d = threadIdx.x;
    if (d < 16) p[d] = proj[(size_t)i * 48 + d];
    __syncthreads();
    const float4* w4 = (const float4*)(Wdt + d * 16);
    float s = bdt[d];
#pragma unroll
    for (int r4 = 0; r4 < 4; r4++) {
        float4 w = w4[r4];
        s += p[r4 * 4 + 0] * w.x + p[r4 * 4 + 1] * w.y +
             p[r4 * 4 + 2] * w.z + p[r4 * 4 + 3] * w.w;
    }
    float sp = fmaxf(s, 0.f) + log1pf(__expf(-fabsf(s)));
    dt[(size_t)i * DI + d] = sp;
}

// ---------------- selective scan ---------------------------------------------
#define ST 128
__global__ void __launch_bounds__(128) k_scan(
    const float* __restrict__ dt, const float* __restrict__ u,
    const float* __restrict__ proj, const float* __restrict__ A_log,
    float* __restrict__ ys) {
    __shared__ float sdt[ST * 8], su[ST * 8], sB[ST * 16], sC[ST * 16], sy[ST * 8];
    int blk = blockIdx.x;
    int b   = blk >> 6;
    int d0  = (blk & 63) * 8;
    int tid  = threadIdx.x;
    int dloc = tid >> 4;
    int n    = tid & 15;
    int d    = d0 + dloc;
    float a = -__expf(A_log[d * NST + n]);
    float h = 0.f;
    size_t base = (size_t)b * LSEQ;
    for (int l0 = 0; l0 < LSEQ; l0 += ST) {
        __syncthreads();
        for (int idx = tid; idx < ST * 8; idx += 128) {
            int j = idx >> 3, dd = idx & 7;
            size_t g = (base + l0 + j) * DI + d0 + dd;
            sdt[idx] = dt[g];
            su[idx]  = u[g];
        }
        for (int idx = tid; idx < ST * 16; idx += 128) {
            int j = idx >> 4, nn = idx & 15;
            size_t g = (base + l0 + j) * 48;
            sB[idx] = proj[g + 16 + nn];
            sC[idx] = proj[g + 32 + nn];
        }
        __syncthreads();
#pragma unroll 4
        for (int j = 0; j < ST; j++) {
            float dtv = sdt[j * 8 + dloc];
            float dA  = __expf(dtv * a);
            h = dA * h + (dtv * su[j * 8 + dloc]) * sB[j * 16 + n];
            float yv = h * sC[j * 16 + n];
            yv += __shfl_xor_sync(~0u, yv, 8);
            yv += __shfl_xor_sync(~0u, yv, 4);
            yv += __shfl_xor_sync(~0u, yv, 2);
            yv += __shfl_xor_sync(~0u, yv, 1);
            if (n == 0) sy[j * 8 + dloc] = yv;
        }
        __syncthreads();
        for (int idx = tid; idx < ST * 8; idx += 128) {
            int j = idx >> 3, dd = idx & 7;
            ys[(base + l0 + j) * DI + d0 + dd] = sy[idx];
        }
    }
}

// ---------------- gate: ym = (ys + u*D) * silu(z) ----------------------------
__global__ void k_gate(float* __restrict__ ym, const float* __restrict__ u,
                       const float* __restrict__ xz, const float* __restrict__ Dv) {
    int i = blockIdx.x * blockDim.x + threadIdx.x;
    if (i >= BL * DI) return;
    int d   = i & (DI - 1);
    int row = i >> 9;
    float zv  = xz[(size_t)row * XZW + DI + d];
    float sil = zv / (1.f + __expf(-zv));
    ym[i] = (ym[i] + u[i] * Dv[d]) * sil;
}

// ================= TF32 tensor-core GEMM (ldmatrix version) ==================
// C(M,N) = A(M,K) @ Bw(N,K)^T (+ epilogue). K%32==0, M%128==0, N%TN==0.
// Block tile 128 x TN, 8 warps as 2(M) x 4(N); warp tile 64 x TN/4.
// EPI: 0 none; 1 bias+gelu; 2 +resid; 3 bias+resid

__device__ __forceinline__ uint32_t f2tf32(float x) {
    uint32_t u;
    asm("cvt.rna.tf32.f32 %0, %1;" : "=r"(u) : "f"(x));
    return u;
}

__device__ __forceinline__ void mma_tf32(float& c0, float& c1, float& c2, float& c3,
                                         uint32_t a0, uint32_t a1, uint32_t a2, uint32_t a3,
                                         uint32_t b0, uint32_t b1) {
    asm volatile(
        "mma.sync.aligned.m16n8k8.row.col.f32.tf32.tf32.f32 "
        "{%0,%1,%2,%3}, {%4,%5,%6,%7}, {%8,%9}, {%0,%1,%2,%3};"
        : "+f"(c0), "+f"(c1), "+f"(c2), "+f"(c3)
        : "r"(a0), "r"(a1), "r"(a2), "r"(a3), "r"(b0), "r"(b1));
}

__device__ __forceinline__ void ldsm4(uint32_t* r, uint32_t addr) {
    asm volatile("ldmatrix.sync.aligned.m8n8.x4.shared.b16 {%0,%1,%2,%3}, [%4];"
                 : "=r"(r[0]), "=r"(r[1]), "=r"(r[2]), "=r"(r[3]) : "r"(addr));
}

template <int EPI, int TN>
__global__ void __launch_bounds__(256) k_tgemm(
    const float* __restrict__ A, const float* __restrict__ Bw,
    const float* __restrict__ bias, const float* __restrict__ resid,
    float* __restrict__ C, int M, int N, int K) {
    constexpr int WN = TN / 4;     // warp N extent (32 or 16)
    constexpr int NI = WN / 8;     // 8-col mma tiles per warp (4 or 2)
    constexpr int NP = NI / 2;     // ldmatrix pairs (2 or 1)
    constexpr int FB = TN / 32;    // B float4 loads per thread (4 or 2)

    // [row][36] pad-4: ldmatrix rows land on distinct banks (36 mod 32 = 4)
    __shared__ uint32_t As[128][36];
    __shared__ uint32_t Bs[TN][36];

    int tid  = threadIdx.x;
    int lane = tid & 31;
    int wid  = tid >> 5;
    int wm   = wid & 1;
    int wn   = wid >> 1;
    int grp  = lane >> 2;
    int l4   = lane & 3;
    int m8   = lane >> 3;    // ldmatrix sub-matrix index 0..3
    int lr8  = lane & 7;

    int row0 = blockIdx.y * 128;
    int col0 = blockIdx.x * TN;

    // gmem staging map
    int ldr[4], ldq[4];
#pragma unroll
    for (int f = 0; f < 4; f++) {
        int idx = tid + 256 * f;
        ldr[f] = idx >> 3;
        ldq[f] = idx & 7;
    }

    // ldmatrix base addresses (bytes into smem)
    uint32_t a_base[4], b_base[NP];
#pragma unroll
    for (int mi = 0; mi < 4; mi++)
        a_base[mi] = (uint32_t)__cvta_generic_to_shared(
            &As[wm * 64 + mi * 16 + lr8 + 8 * (m8 & 1)][(m8 >> 1) * 4]);
#pragma unroll
    for (int p = 0; p < NP; p++)
        b_base[p] = (uint32_t)__cvta_generic_to_shared(
            &Bs[wn * WN + p * 16 + (m8 >> 1) * 8 + lr8][(m8 & 1) * 4]);

    float acc[4][NI][4];
#pragma unroll
    for (int mi = 0; mi < 4; mi++)
#pragma unroll
        for (int ni = 0; ni < NI; ni++)
#pragma unroll
            for (int t = 0; t < 4; t++) acc[mi][ni][t] = 0.f;

    // prefetch first K-tile
    float4 ra[4], rb[FB];
#pragma unroll
    for (int f = 0; f < 4; f++)
        ra[f] = *(const float4*)(A + (size_t)(row0 + ldr[f]) * K + ldq[f] * 4);
#pragma unroll
    for (int f = 0; f < FB; f++)
        rb[f] = *(const float4*)(Bw + (size_t)(col0 + ldr[f]) * K + ldq[f] * 4);

    for (int kt = 0; kt < K; kt += 32) {
#pragma unroll
        for (int f = 0; f < 4; f++) {
            uint4 va = make_uint4(f2tf32(ra[f].x), f2tf32(ra[f].y),
                                  f2tf32(ra[f].z), f2tf32(ra[f].w));
            *(uint4*)&As[ldr[f]][ldq[f] * 4] = va;
        }
#pragma unroll
        for (int f = 0; f < FB; f++) {
            uint4 vb = make_uint4(f2tf32(rb[f].x), f2tf32(rb[f].y),
                                  f2tf32(rb[f].z), f2tf32(rb[f].w));
            *(uint4*)&Bs[ldr[f]][ldq[f] * 4] = vb;
        }
        __syncthreads();

        if (kt + 32 < K) {
#pragma unroll
            for (int f = 0; f < 4; f++)
                ra[f] = *(const float4*)(A + (size_t)(row0 + ldr[f]) * K + kt + 32 + ldq[f] * 4);
#pragma unroll
            for (int f = 0; f < FB; f++)
                rb[f] = *(const float4*)(Bw + (size_t)(col0 + ldr[f]) * K + kt + 32 + ldq[f] * 4);
        }

#pragma unroll
        for (int ks = 0; ks < 4; ks++) {
            uint32_t af[4][4], bf[NI][2];
#pragma unroll
            for (int mi = 0; mi < 4; mi++)
                ldsm4(af[mi], a_base[mi] + ks * 32);
#pragma unroll
            for (int p = 0; p < NP; p++) {
                uint32_t bq[4];
                ldsm4(bq, b_base[p] + ks * 32);
                bf[2 * p][0]     = bq[0];
                bf[2 * p][1]     = bq[1];
                bf[2 * p + 1][0] = bq[2];
                bf[2 * p + 1][1] = bq[3];
            }
#pragma unroll
            for (int mi = 0; mi < 4; mi++)
#pragma unroll
                for (int ni = 0; ni < NI; ni++)
                    mma_tf32(acc[mi][ni][0], acc[mi][ni][1], acc[mi][ni][2], acc[mi][ni][3],
                             af[mi][0], af[mi][1], af[mi][2], af[mi][3],
                             bf[ni][0], bf[ni][1]);
        }
        __syncthreads();
    }

    // epilogue
#pragma unroll
    for (int mi = 0; mi < 4; mi++) {
#pragma unroll
        for (int ni = 0; ni < NI; ni++) {
            int r = row0 + wm * 64 + mi * 16 + grp;
            int c = col0 + wn * WN + ni * 8 + l4 * 2;
#pragma unroll
            for (int half = 0; half < 2; half++) {
                int rr = r + half * 8;
                float v0 = acc[mi][ni][half * 2 + 0];
                float v1 = acc[mi][ni][half * 2 + 1];
                if (EPI == 1) {
                    v0 += bias[c];     v1 += bias[c + 1];
                    v0 = 0.5f * v0 * (1.f + erff(v0 * 0.70710678118654752f));
                    v1 = 0.5f * v1 * (1.f + erff(v1 * 0.70710678118654752f));
                } else if (EPI == 2) {
                    const float2 rv = *(const float2*)(resid + (size_t)rr * N + c);
                    v0 += rv.x; v1 += rv.y;
                } else if (EPI == 3) {
                    const float2 rv = *(const float2*)(resid + (size_t)rr * N + c);
                    v0 += bias[c] + rv.x; v1 += bias[c + 1] + rv.y;
                }
                *(float2*)(C + (size_t)rr * N + c) = make_float2(v0, v1);
            }
        }
    }
}

// ---------------- launcher ---------------------------------------------------
extern "C" void kernel_launch(void* const* d_in, const int* in_sizes, int n_in,
                              void* d_out, int out_size) {
    const float* x      = (const float*)d_in[0];
    const float* gamma  = (const float*)d_in[1];
    const float* beta   = (const float*)d_in[2];
    const float* W_in   = (const float*)d_in[3];
    const float* conv_w = (const float*)d_in[4];
    const float* conv_b = (const float*)d_in[5];
    const float* W_xp   = (const float*)d_in[6];
    const float* W_dt   = (const float*)d_in[7];
    const float* b_dt   = (const float*)d_in[8];
    const float* A_log  = (const float*)d_in[9];
    const float* Dv     = (const float*)d_in[10];
    const float* W_out  = (const float*)d_in[11];
    const float* W1     = (const float*)d_in[12];
    const float* b1     = (const float*)d_in[13];
    const float* W2     = (const float*)d_in[14];
    const float* b2     = (const float*)d_in[15];
    float* out = (float*)d_out;

    float *yn, *xz, *u, *proj, *dt, *ym, *y2, *hid, *y3;
    cudaGetSymbolAddress((void**)&yn,  g_yn);
    cudaGetSymbolAddress((void**)&xz,  g_xz);
    cudaGetSymbolAddress((void**)&u,   g_u);
    cudaGetSymbolAddress((void**)&proj,g_proj);
    cudaGetSymbolAddress((void**)&dt,  g_dt);
    cudaGetSymbolAddress((void**)&ym,  g_ym);
    cudaGetSymbolAddress((void**)&y2,  g_y2);
    cudaGetSymbolAddress((void**)&hid, g_hid);
    cudaGetSymbolAddress((void**)&y3,  g_y3);

    dim3 tb(32, 8);

    // 1) transpose x (B,C,L) -> yn (B,L,C)
    {
        dim3 grid(LSEQ / 32, DIM / 32, BATCH);
        k_transpose<<<grid, tb>>>(x, yn, DIM, LSEQ);
    }
    // 2) layernorm in place
    k_layernorm<<<BL * 32 / 256, 256>>>(yn, gamma, beta);
    // 3) xz = yn @ W_in^T  (8192 x 1024 x 256)
    {
        dim3 grid(XZW / 128, BL / 128);
        k_tgemm<0, 128><<<grid, 256>>>(yn, W_in, nullptr, nullptr, xz, BL, XZW, DIM);
    }
    // 4) conv + silu -> u
    k_conv_silu<<<(BL * DI / 4) / 256, 256>>>(xz, conv_w, conv_b, u);
    // 5) proj = u @ W_xp^T
    k_proj<<<BL / 8, 256>>>(u, W_xp, proj);
    // 6) dt
    k_dt<<<BL, DI>>>(proj, W_dt, b_dt, dt);
    // 7) selective scan -> ym (holds ys)
    k_scan<<<BATCH * (DI / 8), 128>>>(dt, u, proj, A_log, ym);
    // 8) gate
    k_gate<<<(BL * DI) / 256, 256>>>(ym, u, xz, Dv);
    // 9) y2 = ym @ W_out^T + yn   (8192 x 256 x 512), TN=64 -> 256 CTAs
    {
        dim3 grid(DIM / 64, BL / 128);
        k_tgemm<2, 64><<<grid, 256>>>(ym, W_out, nullptr, yn, y2, BL, DIM, DI);
    }
    // 10) hid = gelu(y2 @ W1^T + b1)   (8192 x 1024 x 256)
    {
        dim3 grid(HIDW / 128, BL / 128);
        k_tgemm<1, 128><<<grid, 256>>>(y2, W1, b1, nullptr, hid, BL, HIDW, DIM);
    }
    // 11) y3 = hid @ W2^T + b2 + y2   (8192 x 256 x 1024), TN=64 -> 256 CTAs
    {
        dim3 grid(DIM / 64, BL / 128);
        k_tgemm<3, 64><<<grid, 256>>>(hid, W2, b2, y2, y3, BL, DIM, HIDW);
    }
    // 12) transpose y3 (B,L,C) -> out (B,C,L)
    {
        dim3 grid(DIM / 32, LSEQ / 32, BATCH);
        k_transpose<<<grid, tb>>>(y3, out, LSEQ, DIM);
    }
}

// round 6
// speedup vs baseline: 1.9342x; 1.9342x over previous
#include <cuda_runtime.h>
#include <cuda_bf16.h>
#include <math.h>
#include <stdint.h>

// Problem constants
#define BATCH 2
#define DIM   256
#define HW    64
#define LSEQ  4096          // 64*64
#define BL    8192          // BATCH*LSEQ
#define DI    512           // d_inner
#define NST   16            // d_state
#define RNK   16            // dt_rank
#define XZW   1024          // 2*DI
#define HIDW  1024          // 4*DIM

#define NCHUNK 64
#define CS     64           // chunk size (NCHUNK*CS == LSEQ)
#define SCANW  16384        // BATCH*DI*NST carry lanes

// ---------------- scratch (static device globals; no allocation) -------------
__device__ float g_yn  [(size_t)BL * DIM];
__device__ float g_xz  [(size_t)BL * XZW];
__device__ float g_u   [(size_t)BL * DI];
__device__ float g_proj[(size_t)BL * 48];
__device__ float g_dt  [(size_t)BL * DI];
__device__ float g_ym  [(size_t)BL * DI];
__device__ float g_y2  [(size_t)BL * DIM];
__device__ float g_hid [(size_t)BL * HIDW];
__device__ float g_y3  [(size_t)BL * DIM];
__device__ float g_P   [(size_t)NCHUNK * SCANW];   // chunk dA products
__device__ float g_he  [(size_t)NCHUNK * SCANW];   // chunk local end states
__device__ float g_H   [(size_t)NCHUNK * SCANW];   // chunk carry-in states

// ---------------- transpose: in (B, D1, D2) -> out (B, D2, D1) ---------------
__global__ void k_transpose(const float* __restrict__ in, float* __restrict__ out,
                            int D1, int D2) {
    __shared__ float tile[32][33];
    int b  = blockIdx.z;
    int i0 = blockIdx.y * 32;
    int j0 = blockIdx.x * 32;
    int tx = threadIdx.x, ty = threadIdx.y;
    const float* ip = in  + (size_t)b * D1 * D2;
    float*       op = out + (size_t)b * D1 * D2;
#pragma unroll
    for (int s = 0; s < 32; s += 8)
        tile[ty + s][tx] = ip[(size_t)(i0 + ty + s) * D2 + j0 + tx];
    __syncthreads();
#pragma unroll
    for (int s = 0; s < 32; s += 8)
        op[(size_t)(j0 + ty + s) * D1 + i0 + tx] = tile[tx][ty + s];
}

// ---------------- layernorm ---------------------------------------------------
__global__ void k_layernorm(float* __restrict__ y,
                            const float* __restrict__ gamma,
                            const float* __restrict__ beta) {
    int gw   = (blockIdx.x * blockDim.x + threadIdx.x) >> 5;
    int lane = threadIdx.x & 31;
    if (gw >= BL) return;
    float* row = y + (size_t)gw * DIM;
    float v[8];
    float s = 0.f;
#pragma unroll
    for (int t = 0; t < 8; t++) { v[t] = row[lane + 32 * t]; s += v[t]; }
#pragma unroll
    for (int o = 16; o > 0; o >>= 1) s += __shfl_xor_sync(~0u, s, o);
    float mu = s * (1.f / DIM);
    float var = 0.f;
#pragma unroll
    for (int t = 0; t < 8; t++) { float d = v[t] - mu; var += d * d; }
#pragma unroll
    for (int o = 16; o > 0; o >>= 1) var += __shfl_xor_sync(~0u, var, o);
    float rstd = rsqrtf(var * (1.f / DIM) + 1e-5f);
#pragma unroll
    for (int t = 0; t < 8; t++) {
        int c = lane + 32 * t;
        row[c] = (v[t] - mu) * rstd * gamma[c] + beta[c];
    }
}

// ---------------- causal depthwise conv(4) + silu (scalar, R4-measured best) -
__global__ void k_conv_silu(const float* __restrict__ xz,
                            const float* __restrict__ cw,
                            const float* __restrict__ cb,
                            float* __restrict__ u) {
    int i = blockIdx.x * blockDim.x + threadIdx.x;
    if (i >= BL * DI) return;
    int d    = i & (DI - 1);
    int lrow = i >> 9;
    int l    = lrow & (LSEQ - 1);
    float acc = cb[d];
#pragma unroll
    for (int k = 0; k < 4; k++) {
        int ll = l - 3 + k;
        if (ll >= 0)
            acc += cw[d * 4 + k] * xz[(size_t)(lrow - 3 + k) * XZW + d];
    }
    u[i] = acc / (1.f + __expf(-acc));
}

// ---------------- x-proj: proj(BL,48) = u(BL,512) @ W_xp(48,512)^T ----------
__global__ void k_proj(const float* __restrict__ u,
                       const float* __restrict__ Wxp,
                       float* __restrict__ proj) {
    int gw   = (blockIdx.x * blockDim.x + threadIdx.x) >> 5;
    int lane = threadIdx.x & 31;
    if (gw >= BL) return;
    const float* ur = u + (size_t)gw * DI;
    float ureg[16];
#pragma unroll
    for (int t = 0; t < 16; t++) ureg[t] = ur[lane + 32 * t];
    for (int j = 0; j < 48; j++) {
        const float* w = Wxp + (size_t)j * DI;
        float s = 0.f;
#pragma unroll
        for (int t = 0; t < 16; t++) s += ureg[t] * w[lane + 32 * t];
#pragma unroll
        for (int o = 16; o > 0; o >>= 1) s += __shfl_xor_sync(~0u, s, o);
        if (lane == 0) proj[(size_t)gw * 48 + j] = s;
    }
}

// ---------------- dt = softplus(proj[:, :16] @ W_dt^T + b_dt) ----------------
__global__ void k_dt(const float* __restrict__ proj,
                     const float* __restrict__ Wdt,
                     const float* __restrict__ bdt,
                     float* __restrict__ dt) {
    __shared__ float p[16];
    int i = blockIdx.x;
    int d = threadIdx.x;
    if (d < 16) p[d] = proj[(size_t)i * 48 + d];
    __syncthreads();
    const float4* w4 = (const float4*)(Wdt + d * 16);
    float s = bdt[d];
#pragma unroll
    for (int r4 = 0; r4 < 4; r4++) {
        float4 w = w4[r4];
        s += p[r4 * 4 + 0] * w.x + p[r4 * 4 + 1] * w.y +
             p[r4 * 4 + 2] * w.z + p[r4 * 4 + 3] * w.w;
    }
    float sp = fmaxf(s, 0.f) + log1pf(__expf(-fabsf(s)));
    dt[(size_t)i * DI + d] = sp;
}

// =============== chunked selective scan ======================================
// block = 8 d x 16 n = 128 threads; grid.x = B*64 (d-groups), grid.y = NCHUNK.
// PASS 1: local scan from h=0, emit P = prod(dA) and local end state.
// PASS 3: local scan from carried-in H, emit y via warp-shfl reduce over n.
template <int PASS>
__global__ void __launch_bounds__(128) k_scan_chunk(
    const float* __restrict__ dt, const float* __restrict__ u,
    const float* __restrict__ proj, const float* __restrict__ A_log,
    float* __restrict__ Pout, float* __restrict__ heout,
    const float* __restrict__ Hin, float* __restrict__ ys) {
    __shared__ float sdt[CS * 8], su[CS * 8], sB[CS * 16], sC[CS * 16], sy[CS * 8];
    int blk = blockIdx.x;
    int b   = blk >> 6;
    int d0  = (blk & 63) * 8;
    int chunk = blockIdx.y;
    int tid  = threadIdx.x;
    int dloc = tid >> 4;
    int n    = tid & 15;
    int d    = d0 + dloc;
    float a = -__expf(A_log[d * NST + n]);
    size_t base = (size_t)b * LSEQ + (size_t)chunk * CS;

    for (int idx = tid; idx < CS * 8; idx += 128) {
        int j = idx >> 3, dd = idx & 7;
        size_t g = (base + j) * DI + d0 + dd;
        sdt[idx] = dt[g];
        su[idx]  = u[g];
    }
    for (int idx = tid; idx < CS * 16; idx += 128) {
        int j = idx >> 4, nn = idx & 15;
        size_t g = (base + j) * 48;
        sB[idx] = proj[g + 16 + nn];
        if (PASS == 3) sC[idx] = proj[g + 32 + nn];
    }
    __syncthreads();

    size_t sidx = (size_t)chunk * SCANW + (size_t)b * (DI * NST) + d * NST + n;

    if (PASS == 1) {
        float h = 0.f, Pr = 1.f;
#pragma unroll 8
        for (int j = 0; j < CS; j++) {
            float dtv = sdt[j * 8 + dloc];
            float dA  = __expf(dtv * a);
            h  = dA * h + (dtv * su[j * 8 + dloc]) * sB[j * 16 + n];
            Pr *= dA;
        }
        Pout[sidx] = Pr;
        heout[sidx] = h;
    } else {
        float h = Hin[sidx];
#pragma unroll 4
        for (int j = 0; j < CS; j++) {
            float dtv = sdt[j * 8 + dloc];
            float dA  = __expf(dtv * a);
            h = dA * h + (dtv * su[j * 8 + dloc]) * sB[j * 16 + n];
            float yv = h * sC[j * 16 + n];
            yv += __shfl_xor_sync(~0u, yv, 8);
            yv += __shfl_xor_sync(~0u, yv, 4);
            yv += __shfl_xor_sync(~0u, yv, 2);
            yv += __shfl_xor_sync(~0u, yv, 1);
            if (n == 0) sy[j * 8 + dloc] = yv;
        }
        __syncthreads();
        for (int idx = tid; idx < CS * 8; idx += 128) {
            int j = idx >> 3, dd = idx & 7;
            ys[(base + j) * DI + d0 + dd] = sy[idx];
        }
    }
}

// Pass 2: per-(b,d,n) carry scan over the 64 chunks.
__global__ void k_scan_carry(const float* __restrict__ P,
                             const float* __restrict__ he,
                             float* __restrict__ H) {
    int tid = blockIdx.x * blockDim.x + threadIdx.x;
    if (tid >= SCANW) return;
    float Hc = 0.f;
#pragma unroll 8
    for (int c = 0; c < NCHUNK; c++) {
        size_t idx = (size_t)c * SCANW + tid;
        H[idx] = Hc;
        Hc = P[idx] * Hc + he[idx];
    }
}

// ---------------- gate: ym = (ys + u*D) * silu(z) ----------------------------
__global__ void k_gate(float* __restrict__ ym, const float* __restrict__ u,
                       const float* __restrict__ xz, const float* __restrict__ Dv) {
    int i = blockIdx.x * blockDim.x + threadIdx.x;
    if (i >= BL * DI) return;
    int d   = i & (DI - 1);
    int row = i >> 9;
    float zv  = xz[(size_t)row * XZW + DI + d];
    float sil = zv / (1.f + __expf(-zv));
    ym[i] = (ym[i] + u[i] * Dv[d]) * sil;
}

// ================= TF32 tensor-core GEMM (ldmatrix version) ==================
__device__ __forceinline__ uint32_t f2tf32(float x) {
    uint32_t u;
    asm("cvt.rna.tf32.f32 %0, %1;" : "=r"(u) : "f"(x));
    return u;
}

__device__ __forceinline__ void mma_tf32(float& c0, float& c1, float& c2, float& c3,
                                         uint32_t a0, uint32_t a1, uint32_t a2, uint32_t a3,
                                         uint32_t b0, uint32_t b1) {
    asm volatile(
        "mma.sync.aligned.m16n8k8.row.col.f32.tf32.tf32.f32 "
        "{%0,%1,%2,%3}, {%4,%5,%6,%7}, {%8,%9}, {%0,%1,%2,%3};"
        : "+f"(c0), "+f"(c1), "+f"(c2), "+f"(c3)
        : "r"(a0), "r"(a1), "r"(a2), "r"(a3), "r"(b0), "r"(b1));
}

__device__ __forceinline__ void ldsm4(uint32_t* r, uint32_t addr) {
    asm volatile("ldmatrix.sync.aligned.m8n8.x4.shared.b16 {%0,%1,%2,%3}, [%4];"
                 : "=r"(r[0]), "=r"(r[1]), "=r"(r[2]), "=r"(r[3]) : "r"(addr));
}

template <int EPI, int TN>
__global__ void __launch_bounds__(256) k_tgemm(
    const float* __restrict__ A, const float* __restrict__ Bw,
    const float* __restrict__ bias, const float* __restrict__ resid,
    float* __restrict__ C, int M, int N, int K) {
    constexpr int WN = TN / 4;
    constexpr int NI = WN / 8;
    constexpr int NP = NI / 2;
    constexpr int FB = TN / 32;

    __shared__ uint32_t As[128][36];
    __shared__ uint32_t Bs[TN][36];

    int tid  = threadIdx.x;
    int lane = tid & 31;
    int wid  = tid >> 5;
    int wm   = wid & 1;
    int wn   = wid >> 1;
    int grp  = lane >> 2;
    int l4   = lane & 3;
    int m8   = lane >> 3;
    int lr8  = lane & 7;

    int row0 = blockIdx.y * 128;
    int col0 = blockIdx.x * TN;

    int ldr[4], ldq[4];
#pragma unroll
    for (int f = 0; f < 4; f++) {
        int idx = tid + 256 * f;
        ldr[f] = idx >> 3;
        ldq[f] = idx & 7;
    }

    uint32_t a_base[4], b_base[NP];
#pragma unroll
    for (int mi = 0; mi < 4; mi++)
        a_base[mi] = (uint32_t)__cvta_generic_to_shared(
            &As[wm * 64 + mi * 16 + lr8 + 8 * (m8 & 1)][(m8 >> 1) * 4]);
#pragma unroll
    for (int p = 0; p < NP; p++)
        b_base[p] = (uint32_t)__cvta_generic_to_shared(
            &Bs[wn * WN + p * 16 + (m8 >> 1) * 8 + lr8][(m8 & 1) * 4]);

    float acc[4][NI][4];
#pragma unroll
    for (int mi = 0; mi < 4; mi++)
#pragma unroll
        for (int ni = 0; ni < NI; ni++)
#pragma unroll
            for (int t = 0; t < 4; t++) acc[mi][ni][t] = 0.f;

    float4 ra[4], rb[FB];
#pragma unroll
    for (int f = 0; f < 4; f++)
        ra[f] = *(const float4*)(A + (size_t)(row0 + ldr[f]) * K + ldq[f] * 4);
#pragma unroll
    for (int f = 0; f < FB; f++)
        rb[f] = *(const float4*)(Bw + (size_t)(col0 + ldr[f]) * K + ldq[f] * 4);

    for (int kt = 0; kt < K; kt += 32) {
#pragma unroll
        for (int f = 0; f < 4; f++) {
            uint4 va = make_uint4(f2tf32(ra[f].x), f2tf32(ra[f].y),
                                  f2tf32(ra[f].z), f2tf32(ra[f].w));
            *(uint4*)&As[ldr[f]][ldq[f] * 4] = va;
        }
#pragma unroll
        for (int f = 0; f < FB; f++) {
            uint4 vb = make_uint4(f2tf32(rb[f].x), f2tf32(rb[f].y),
                                  f2tf32(rb[f].z), f2tf32(rb[f].w));
            *(uint4*)&Bs[ldr[f]][ldq[f] * 4] = vb;
        }
        __syncthreads();

        if (kt + 32 < K) {
#pragma unroll
            for (int f = 0; f < 4; f++)
                ra[f] = *(const float4*)(A + (size_t)(row0 + ldr[f]) * K + kt + 32 + ldq[f] * 4);
#pragma unroll
            for (int f = 0; f < FB; f++)
                rb[f] = *(const float4*)(Bw + (size_t)(col0 + ldr[f]) * K + kt + 32 + ldq[f] * 4);
        }

#pragma unroll
        for (int ks = 0; ks < 4; ks++) {
            uint32_t af[4][4], bf[NI][2];
#pragma unroll
            for (int mi = 0; mi < 4; mi++)
                ldsm4(af[mi], a_base[mi] + ks * 32);
#pragma unroll
            for (int p = 0; p < NP; p++) {
                uint32_t bq[4];
                ldsm4(bq, b_base[p] + ks * 32);
                bf[2 * p][0]     = bq[0];
                bf[2 * p][1]     = bq[1];
                bf[2 * p + 1][0] = bq[2];
                bf[2 * p + 1][1] = bq[3];
            }
#pragma unroll
            for (int mi = 0; mi < 4; mi++)
#pragma unroll
                for (int ni = 0; ni < NI; ni++)
                    mma_tf32(acc[mi][ni][0], acc[mi][ni][1], acc[mi][ni][2], acc[mi][ni][3],
                             af[mi][0], af[mi][1], af[mi][2], af[mi][3],
                             bf[ni][0], bf[ni][1]);
        }
        __syncthreads();
    }

#pragma unroll
    for (int mi = 0; mi < 4; mi++) {
#pragma unroll
        for (int ni = 0; ni < NI; ni++) {
            int r = row0 + wm * 64 + mi * 16 + grp;
            int c = col0 + wn * WN + ni * 8 + l4 * 2;
#pragma unroll
            for (int half = 0; half < 2; half++) {
                int rr = r + half * 8;
                float v0 = acc[mi][ni][half * 2 + 0];
                float v1 = acc[mi][ni][half * 2 + 1];
                if (EPI == 1) {
                    v0 += bias[c];     v1 += bias[c + 1];
                    v0 = 0.5f * v0 * (1.f + erff(v0 * 0.70710678118654752f));
                    v1 = 0.5f * v1 * (1.f + erff(v1 * 0.70710678118654752f));
                } else if (EPI == 2) {
                    const float2 rv = *(const float2*)(resid + (size_t)rr * N + c);
                    v0 += rv.x; v1 += rv.y;
                } else if (EPI == 3) {
                    const float2 rv = *(const float2*)(resid + (size_t)rr * N + c);
                    v0 += bias[c] + rv.x; v1 += bias[c + 1] + rv.y;
                }
                *(float2*)(C + (size_t)rr * N + c) = make_float2(v0, v1);
            }
        }
    }
}

// ---------------- launcher ---------------------------------------------------
extern "C" void kernel_launch(void* const* d_in, const int* in_sizes, int n_in,
                              void* d_out, int out_size) {
    const float* x      = (const float*)d_in[0];
    const float* gamma  = (const float*)d_in[1];
    const float* beta   = (const float*)d_in[2];
    const float* W_in   = (const float*)d_in[3];
    const float* conv_w = (const float*)d_in[4];
    const float* conv_b = (const float*)d_in[5];
    const float* W_xp   = (const float*)d_in[6];
    const float* W_dt   = (const float*)d_in[7];
    const float* b_dt   = (const float*)d_in[8];
    const float* A_log  = (const float*)d_in[9];
    const float* Dv     = (const float*)d_in[10];
    const float* W_out  = (const float*)d_in[11];
    const float* W1     = (const float*)d_in[12];
    const float* b1     = (const float*)d_in[13];
    const float* W2     = (const float*)d_in[14];
    const float* b2     = (const float*)d_in[15];
    float* out = (float*)d_out;

    float *yn, *xz, *u, *proj, *dt, *ym, *y2, *hid, *y3, *Pb, *he, *Hb;
    cudaGetSymbolAddress((void**)&yn,  g_yn);
    cudaGetSymbolAddress((void**)&xz,  g_xz);
    cudaGetSymbolAddress((void**)&u,   g_u);
    cudaGetSymbolAddress((void**)&proj,g_proj);
    cudaGetSymbolAddress((void**)&dt,  g_dt);
    cudaGetSymbolAddress((void**)&ym,  g_ym);
    cudaGetSymbolAddress((void**)&y2,  g_y2);
    cudaGetSymbolAddress((void**)&hid, g_hid);
    cudaGetSymbolAddress((void**)&y3,  g_y3);
    cudaGetSymbolAddress((void**)&Pb,  g_P);
    cudaGetSymbolAddress((void**)&he,  g_he);
    cudaGetSymbolAddress((void**)&Hb,  g_H);

    dim3 tb(32, 8);

    // 1) transpose x (B,C,L) -> yn (B,L,C)
    {
        dim3 grid(LSEQ / 32, DIM / 32, BATCH);
        k_transpose<<<grid, tb>>>(x, yn, DIM, LSEQ);
    }
    // 2) layernorm in place
    k_layernorm<<<BL * 32 / 256, 256>>>(yn, gamma, beta);
    // 3) xz = yn @ W_in^T
    {
        dim3 grid(XZW / 128, BL / 128);
        k_tgemm<0, 128><<<grid, 256>>>(yn, W_in, nullptr, nullptr, xz, BL, XZW, DIM);
    }
    // 4) conv + silu -> u
    k_conv_silu<<<(BL * DI) / 256, 256>>>(xz, conv_w, conv_b, u);
    // 5) proj = u @ W_xp^T
    k_proj<<<BL / 8, 256>>>(u, W_xp, proj);
    // 6) dt
    k_dt<<<BL, DI>>>(proj, W_dt, b_dt, dt);
    // 7) chunked selective scan -> ym
    {
        dim3 grid(BATCH * (DI / 8), NCHUNK);
        k_scan_chunk<1><<<grid, 128>>>(dt, u, proj, A_log, Pb, he, nullptr, nullptr);
        k_scan_carry<<<SCANW / 256, 256>>>(Pb, he, Hb);
        k_scan_chunk<3><<<grid, 128>>>(dt, u, proj, A_log, nullptr, nullptr, Hb, ym);
    }
    // 8) gate
    k_gate<<<(BL * DI) / 256, 256>>>(ym, u, xz, Dv);
    // 9) y2 = ym @ W_out^T + yn
    {
        dim3 grid(DIM / 64, BL / 128);
        k_tgemm<2, 64><<<grid, 256>>>(ym, W_out, nullptr, yn, y2, BL, DIM, DI);
    }
    // 10) hid = gelu(y2 @ W1^T + b1)
    {
        dim3 grid(HIDW / 128, BL / 128);
        k_tgemm<1, 128><<<grid, 256>>>(y2, W1, b1, nullptr, hid, BL, HIDW, DIM);
    }
    // 11) y3 = hid @ W2^T + b2 + y2
    {
        dim3 grid(DIM / 64, BL / 128);
        k_tgemm<3, 64><<<grid, 256>>>(hid, W2, b2, y2, y3, BL, DIM, HIDW);
    }
    // 12) transpose y3 (B,L,C) -> out (B,C,L)
    {
        dim3 grid(DIM / 32, LSEQ / 32, BATCH);
        k_transpose<<<grid, tb>>>(y3, out, LSEQ, DIM);
    }
}

// round 7
// speedup vs baseline: 1.9592x; 1.0129x over previous
#include <cuda_runtime.h>
#include <cuda_bf16.h>
#include <math.h>
#include <stdint.h>

// Problem constants
#define BATCH 2
#define DIM   256
#define HW    64
#define LSEQ  4096          // 64*64
#define BL    8192          // BATCH*LSEQ
#define DI    512           // d_inner
#define NST   16            // d_state
#define RNK   16            // dt_rank
#define XZW   1024          // 2*DI
#define HIDW  1024          // 4*DIM

#define NCHUNK 64
#define CS     64
#define SCANW  16384        // BATCH*DI*NST carry lanes

// ---------------- scratch (static device globals; no allocation) -------------
__device__ float g_yn  [(size_t)BL * DIM];
__device__ float g_xz  [(size_t)BL * XZW];
__device__ float g_u   [(size_t)BL * DI];
__device__ float g_proj[(size_t)BL * 48];
__device__ float g_dt  [(size_t)BL * DI];
__device__ float g_ym  [(size_t)BL * DI];
__device__ float g_y2  [(size_t)BL * DIM];
__device__ float g_hid [(size_t)BL * HIDW];
__device__ float g_y3  [(size_t)BL * DIM];
__device__ float g_P   [(size_t)NCHUNK * SCANW];
__device__ float g_he  [(size_t)NCHUNK * SCANW];
__device__ float g_H   [(size_t)NCHUNK * SCANW];

// ---------------- transpose: in (B, D1, D2) -> out (B, D2, D1) ---------------
__global__ void k_transpose(const float* __restrict__ in, float* __restrict__ out,
                            int D1, int D2) {
    __shared__ float tile[32][33];
    int b  = blockIdx.z;
    int i0 = blockIdx.y * 32;
    int j0 = blockIdx.x * 32;
    int tx = threadIdx.x, ty = threadIdx.y;
    const float* ip = in  + (size_t)b * D1 * D2;
    float*       op = out + (size_t)b * D1 * D2;
#pragma unroll
    for (int s = 0; s < 32; s += 8)
        tile[ty + s][tx] = ip[(size_t)(i0 + ty + s) * D2 + j0 + tx];
    __syncthreads();
#pragma unroll
    for (int s = 0; s < 32; s += 8)
        op[(size_t)(j0 + ty + s) * D1 + i0 + tx] = tile[tx][ty + s];
}

// ---------------- layernorm ---------------------------------------------------
__global__ void k_layernorm(float* __restrict__ y,
                            const float* __restrict__ gamma,
                            const float* __restrict__ beta) {
    int gw   = (blockIdx.x * blockDim.x + threadIdx.x) >> 5;
    int lane = threadIdx.x & 31;
    if (gw >= BL) return;
    float* row = y + (size_t)gw * DIM;
    float v[8];
    float s = 0.f;
#pragma unroll
    for (int t = 0; t < 8; t++) { v[t] = row[lane + 32 * t]; s += v[t]; }
#pragma unroll
    for (int o = 16; o > 0; o >>= 1) s += __shfl_xor_sync(~0u, s, o);
    float mu = s * (1.f / DIM);
    float var = 0.f;
#pragma unroll
    for (int t = 0; t < 8; t++) { float d = v[t] - mu; var += d * d; }
#pragma unroll
    for (int o = 16; o > 0; o >>= 1) var += __shfl_xor_sync(~0u, var, o);
    float rstd = rsqrtf(var * (1.f / DIM) + 1e-5f);
#pragma unroll
    for (int t = 0; t < 8; t++) {
        int c = lane + 32 * t;
        row[c] = (v[t] - mu) * rstd * gamma[c] + beta[c];
    }
}

// ---------------- causal depthwise conv(4) + silu ----------------------------
__global__ void k_conv_silu(const float* __restrict__ xz,
                            const float* __restrict__ cw,
                            const float* __restrict__ cb,
                            float* __restrict__ u) {
    int i = blockIdx.x * blockDim.x + threadIdx.x;
    if (i >= BL * DI) return;
    int d    = i & (DI - 1);
    int lrow = i >> 9;
    int l    = lrow & (LSEQ - 1);
    float acc = cb[d];
#pragma unroll
    for (int k = 0; k < 4; k++) {
        int ll = l - 3 + k;
        if (ll >= 0)
            acc += cw[d * 4 + k] * xz[(size_t)(lrow - 3 + k) * XZW + d];
    }
    u[i] = acc / (1.f + __expf(-acc));
}

// ---------------- x-proj: proj(BL,48) = u(BL,512) @ W_xp(48,512)^T ----------
__global__ void k_proj(const float* __restrict__ u,
                       const float* __restrict__ Wxp,
                       float* __restrict__ proj) {
    int gw   = (blockIdx.x * blockDim.x + threadIdx.x) >> 5;
    int lane = threadIdx.x & 31;
    if (gw >= BL) return;
    const float* ur = u + (size_t)gw * DI;
    float ureg[16];
#pragma unroll
    for (int t = 0; t < 16; t++) ureg[t] = ur[lane + 32 * t];
    for (int j = 0; j < 48; j++) {
        const float* w = Wxp + (size_t)j * DI;
        float s = 0.f;
#pragma unroll
        for (int t = 0; t < 16; t++) s += ureg[t] * w[lane + 32 * t];
#pragma unroll
        for (int o = 16; o > 0; o >>= 1) s += __shfl_xor_sync(~0u, s, o);
        if (lane == 0) proj[(size_t)gw * 48 + j] = s;
    }
}

// ---------------- dt = softplus(proj[:, :16] @ W_dt^T + b_dt) ----------------
__global__ void k_dt(const float* __restrict__ proj,
                     const float* __restrict__ Wdt,
                     const float* __restrict__ bdt,
                     float* __restrict__ dt) {
    __shared__ float p[16];
    int i = blockIdx.x;
    int d = threadIdx.x;
    if (d < 16) p[d] = proj[(size_t)i * 48 + d];
    __syncthreads();
    const float4* w4 = (const float4*)(Wdt + d * 16);
    float s = bdt[d];
#pragma unroll
    for (int r4 = 0; r4 < 4; r4++) {
        float4 w = w4[r4];
        s += p[r4 * 4 + 0] * w.x + p[r4 * 4 + 1] * w.y +
             p[r4 * 4 + 2] * w.z + p[r4 * 4 + 3] * w.w;
    }
    float sp = fmaxf(s, 0.f) + log1pf(__expf(-fabsf(s)));
    dt[(size_t)i * DI + d] = sp;
}

// =============== chunked selective scan ======================================
// PASS 1: local scan from h=0, emit P = prod(dA) and local end state.
// PASS 3: local scan from carried-in H, fused gate -> writes ym directly.
template <int PASS>
__global__ void __launch_bounds__(128) k_scan_chunk(
    const float* __restrict__ dt, const float* __restrict__ u,
    const float* __restrict__ proj, const float* __restrict__ A_log,
    float* __restrict__ Pout, float* __restrict__ heout,
    const float* __restrict__ Hin, float* __restrict__ ys,
    const float* __restrict__ xz, const float* __restrict__ Dv) {
    __shared__ float sdt[CS * 8], su[CS * 8], sB[CS * 16], sC[CS * 16], sy[CS * 8];
    int blk = blockIdx.x;
    int b   = blk >> 6;
    int d0  = (blk & 63) * 8;
    int chunk = blockIdx.y;
    int tid  = threadIdx.x;
    int dloc = tid >> 4;
    int n    = tid & 15;
    int d    = d0 + dloc;
    float a = -__expf(A_log[d * NST + n]);
    size_t base = (size_t)b * LSEQ + (size_t)chunk * CS;

    for (int idx = tid; idx < CS * 8; idx += 128) {
        int j = idx >> 3, dd = idx & 7;
        size_t g = (base + j) * DI + d0 + dd;
        sdt[idx] = dt[g];
        su[idx]  = u[g];
    }
    for (int idx = tid; idx < CS * 16; idx += 128) {
        int j = idx >> 4, nn = idx & 15;
        size_t g = (base + j) * 48;
        sB[idx] = proj[g + 16 + nn];
        if (PASS == 3) sC[idx] = proj[g + 32 + nn];
    }
    __syncthreads();

    size_t sidx = (size_t)chunk * SCANW + (size_t)b * (DI * NST) + d * NST + n;

    if (PASS == 1) {
        float h = 0.f, Pr = 1.f;
#pragma unroll 8
        for (int j = 0; j < CS; j++) {
            float dtv = sdt[j * 8 + dloc];
            float dA  = __expf(dtv * a);
            h  = dA * h + (dtv * su[j * 8 + dloc]) * sB[j * 16 + n];
            Pr *= dA;
        }
        Pout[sidx] = Pr;
        heout[sidx] = h;
    } else {
        float h = Hin[sidx];
#pragma unroll 4
        for (int j = 0; j < CS; j++) {
            float dtv = sdt[j * 8 + dloc];
            float dA  = __expf(dtv * a);
            h = dA * h + (dtv * su[j * 8 + dloc]) * sB[j * 16 + n];
            float yv = h * sC[j * 16 + n];
            yv += __shfl_xor_sync(~0u, yv, 8);
            yv += __shfl_xor_sync(~0u, yv, 4);
            yv += __shfl_xor_sync(~0u, yv, 2);
            yv += __shfl_xor_sync(~0u, yv, 1);
            if (n == 0) sy[j * 8 + dloc] = yv;
        }
        __syncthreads();
        // fused gate: ym = (ys + u*D) * silu(z)
        for (int idx = tid; idx < CS * 8; idx += 128) {
            int j = idx >> 3, dd = idx & 7;
            int dg = d0 + dd;
            float zv  = xz[(base + j) * XZW + DI + dg];
            float sil = zv / (1.f + __expf(-zv));
            ys[(base + j) * DI + dg] = (sy[idx] + su[idx] * Dv[dg]) * sil;
        }
    }
}

// Pass 2: per-(b,d,n) carry scan over the 64 chunks.
__global__ void k_scan_carry(const float* __restrict__ P,
                             const float* __restrict__ he,
                             float* __restrict__ H) {
    int tid = blockIdx.x * blockDim.x + threadIdx.x;
    if (tid >= SCANW) return;
    float Hc = 0.f;
#pragma unroll 8
    for (int c = 0; c < NCHUNK; c++) {
        size_t idx = (size_t)c * SCANW + tid;
        H[idx] = Hc;
        Hc = P[idx] * Hc + he[idx];
    }
}

// ================= TF32 tensor-core GEMM (double-buffered pipeline) ==========
__device__ __forceinline__ uint32_t f2tf32(float x) {
    uint32_t u;
    asm("cvt.rna.tf32.f32 %0, %1;" : "=r"(u) : "f"(x));
    return u;
}

__device__ __forceinline__ void mma_tf32(float& c0, float& c1, float& c2, float& c3,
                                         uint32_t a0, uint32_t a1, uint32_t a2, uint32_t a3,
                                         uint32_t b0, uint32_t b1) {
    asm volatile(
        "mma.sync.aligned.m16n8k8.row.col.f32.tf32.tf32.f32 "
        "{%0,%1,%2,%3}, {%4,%5,%6,%7}, {%8,%9}, {%0,%1,%2,%3};"
        : "+f"(c0), "+f"(c1), "+f"(c2), "+f"(c3)
        : "r"(a0), "r"(a1), "r"(a2), "r"(a3), "r"(b0), "r"(b1));
}

__device__ __forceinline__ void ldsm4(uint32_t* r, uint32_t addr) {
    asm volatile("ldmatrix.sync.aligned.m8n8.x4.shared.b16 {%0,%1,%2,%3}, [%4];"
                 : "=r"(r[0]), "=r"(r[1]), "=r"(r[2]), "=r"(r[3]) : "r"(addr));
}

// C(M,N) = A(M,K) @ Bw(N,K)^T (+ epilogue). K%32==0, M%128==0, N%TN==0.
// EPI: 0 none; 1 bias+gelu; 2 +resid; 3 bias+resid
template <int EPI, int TN>
__global__ void __launch_bounds__(256) k_tgemm(
    const float* __restrict__ A, const float* __restrict__ Bw,
    const float* __restrict__ bias, const float* __restrict__ resid,
    float* __restrict__ C, int M, int N, int K) {
    constexpr int WN  = TN / 4;
    constexpr int NI  = WN / 8;
    constexpr int NP  = NI / 2;
    constexpr int FB  = TN / 32;
    constexpr int AW  = 128 * 36;          // words per As buffer
    constexpr int BWD = TN * 36;           // words per Bs buffer
    constexpr int BUFW = AW + BWD;         // words per (As+Bs) buffer

    extern __shared__ uint32_t sm[];       // 2 * BUFW words

    int tid  = threadIdx.x;
    int lane = tid & 31;
    int wid  = tid >> 5;
    int wm   = wid & 1;
    int wn   = wid >> 1;
    int grp  = lane >> 2;
    int l4   = lane & 3;
    int m8   = lane >> 3;
    int lr8  = lane & 7;

    int row0 = blockIdx.y * 128;
    int col0 = blockIdx.x * TN;

    int ldr[4], ldq[4];
#pragma unroll
    for (int f = 0; f < 4; f++) {
        int idx = tid + 256 * f;
        ldr[f] = idx >> 3;
        ldq[f] = idx & 7;
    }

    // ldmatrix base addresses in buffer 0 (bytes); buffer 1 = +BUFW*4
    uint32_t a_base[4], b_base[NP];
#pragma unroll
    for (int mi = 0; mi < 4; mi++)
        a_base[mi] = (uint32_t)__cvta_generic_to_shared(
            &sm[(wm * 64 + mi * 16 + lr8 + 8 * (m8 & 1)) * 36 + (m8 >> 1) * 4]);
#pragma unroll
    for (int p = 0; p < NP; p++)
        b_base[p] = (uint32_t)__cvta_generic_to_shared(
            &sm[AW + (wn * WN + p * 16 + (m8 >> 1) * 8 + lr8) * 36 + (m8 & 1) * 4]);

    const uint32_t bufB = BUFW * 4;

    float acc[4][NI][4];
#pragma unroll
    for (int mi = 0; mi < 4; mi++)
#pragma unroll
        for (int ni = 0; ni < NI; ni++)
#pragma unroll
            for (int t = 0; t < 4; t++) acc[mi][ni][t] = 0.f;

    // prologue: load + stage tile 0 into buffer 0
    float4 ra[4], rb[FB];
#pragma unroll
    for (int f = 0; f < 4; f++)
        ra[f] = *(const float4*)(A + (size_t)(row0 + ldr[f]) * K + ldq[f] * 4);
#pragma unroll
    for (int f = 0; f < FB; f++)
        rb[f] = *(const float4*)(Bw + (size_t)(col0 + ldr[f]) * K + ldq[f] * 4);
#pragma unroll
    for (int f = 0; f < 4; f++)
        *(uint4*)&sm[ldr[f] * 36 + ldq[f] * 4] =
            make_uint4(f2tf32(ra[f].x), f2tf32(ra[f].y), f2tf32(ra[f].z), f2tf32(ra[f].w));
#pragma unroll
    for (int f = 0; f < FB; f++)
        *(uint4*)&sm[AW + ldr[f] * 36 + ldq[f] * 4] =
            make_uint4(f2tf32(rb[f].x), f2tf32(rb[f].y), f2tf32(rb[f].z), f2tf32(rb[f].w));
    __syncthreads();

    int buf = 0;
    for (int kt = 0; kt < K; kt += 32) {
        bool more = (kt + 32) < K;
        if (more) {
#pragma unroll
            for (int f = 0; f < 4; f++)
                ra[f] = *(const float4*)(A + (size_t)(row0 + ldr[f]) * K + kt + 32 + ldq[f] * 4);
#pragma unroll
            for (int f = 0; f < FB; f++)
                rb[f] = *(const float4*)(Bw + (size_t)(col0 + ldr[f]) * K + kt + 32 + ldq[f] * 4);
        }

        uint32_t boff = buf * bufB;
#pragma unroll
        for (int ks = 0; ks < 4; ks++) {
            uint32_t af[4][4], bf[NI][2];
#pragma unroll
            for (int mi = 0; mi < 4; mi++)
                ldsm4(af[mi], a_base[mi] + boff + ks * 32);
#pragma unroll
            for (int p = 0; p < NP; p++) {
                uint32_t bq[4];
                ldsm4(bq, b_base[p] + boff + ks * 32);
                bf[2 * p][0]     = bq[0];
                bf[2 * p][1]     = bq[1];
                bf[2 * p + 1][0] = bq[2];
                bf[2 * p + 1][1] = bq[3];
            }
#pragma unroll
            for (int mi = 0; mi < 4; mi++)
#pragma unroll
                for (int ni = 0; ni < NI; ni++)
                    mma_tf32(acc[mi][ni][0], acc[mi][ni][1], acc[mi][ni][2], acc[mi][ni][3],
                             af[mi][0], af[mi][1], af[mi][2], af[mi][3],
                             bf[ni][0], bf[ni][1]);
        }

        if (more) {
            uint32_t w = (buf ^ 1) * BUFW;
#pragma unroll
            for (int f = 0; f < 4; f++)
                *(uint4*)&sm[w + ldr[f] * 36 + ldq[f] * 4] =
                    make_uint4(f2tf32(ra[f].x), f2tf32(ra[f].y), f2tf32(ra[f].z), f2tf32(ra[f].w));
#pragma unroll
            for (int f = 0; f < FB; f++)
                *(uint4*)&sm[w + AW + ldr[f] * 36 + ldq[f] * 4] =
                    make_uint4(f2tf32(rb[f].x), f2tf32(rb[f].y), f2tf32(rb[f].z), f2tf32(rb[f].w));
        }
        __syncthreads();
        buf ^= 1;
    }

    // epilogue
#pragma unroll
    for (int mi = 0; mi < 4; mi++) {
#pragma unroll
        for (int ni = 0; ni < NI; ni++) {
            int r = row0 + wm * 64 + mi * 16 + grp;
            int c = col0 + wn * WN + ni * 8 + l4 * 2;
#pragma unroll
            for (int half = 0; half < 2; half++) {
                int rr = r + half * 8;
                float v0 = acc[mi][ni][half * 2 + 0];
                float v1 = acc[mi][ni][half * 2 + 1];
                if (EPI == 1) {
                    v0 += bias[c];     v1 += bias[c + 1];
                    v0 = 0.5f * v0 * (1.f + erff(v0 * 0.70710678118654752f));
                    v1 = 0.5f * v1 * (1.f + erff(v1 * 0.70710678118654752f));
                } else if (EPI == 2) {
                    const float2 rv = *(const float2*)(resid + (size_t)rr * N + c);
                    v0 += rv.x; v1 += rv.y;
                } else if (EPI == 3) {
                    const float2 rv = *(const float2*)(resid + (size_t)rr * N + c);
                    v0 += bias[c] + rv.x; v1 += bias[c + 1] + rv.y;
                }
                *(float2*)(C + (size_t)rr * N + c) = make_float2(v0, v1);
            }
        }
    }
}

#define SMEM128 ((2 * (128 * 36 + 128 * 36)) * 4)   // 73728 B
#define SMEM64  ((2 * (128 * 36 + 64 * 36)) * 4)    // 55296 B

// ---------------- launcher ---------------------------------------------------
extern "C" void kernel_launch(void* const* d_in, const int* in_sizes, int n_in,
                              void* d_out, int out_size) {
    const float* x      = (const float*)d_in[0];
    const float* gamma  = (const float*)d_in[1];
    const float* beta   = (const float*)d_in[2];
    const float* W_in   = (const float*)d_in[3];
    const float* conv_w = (const float*)d_in[4];
    const float* conv_b = (const float*)d_in[5];
    const float* W_xp   = (const float*)d_in[6];
    const float* W_dt   = (const float*)d_in[7];
    const float* b_dt   = (const float*)d_in[8];
    const float* A_log  = (const float*)d_in[9];
    const float* Dv     = (const float*)d_in[10];
    const float* W_out  = (const float*)d_in[11];
    const float* W1     = (const float*)d_in[12];
    const float* b1     = (const float*)d_in[13];
    const float* W2     = (const float*)d_in[14];
    const float* b2     = (const float*)d_in[15];
    float* out = (float*)d_out;

    float *yn, *xz, *u, *proj, *dt, *ym, *y2, *hid, *y3, *Pb, *he, *Hb;
    cudaGetSymbolAddress((void**)&yn,  g_yn);
    cudaGetSymbolAddress((void**)&xz,  g_xz);
    cudaGetSymbolAddress((void**)&u,   g_u);
    cudaGetSymbolAddress((void**)&proj,g_proj);
    cudaGetSymbolAddress((void**)&dt,  g_dt);
    cudaGetSymbolAddress((void**)&ym,  g_ym);
    cudaGetSymbolAddress((void**)&y2,  g_y2);
    cudaGetSymbolAddress((void**)&hid, g_hid);
    cudaGetSymbolAddress((void**)&y3,  g_y3);
    cudaGetSymbolAddress((void**)&Pb,  g_P);
    cudaGetSymbolAddress((void**)&he,  g_he);
    cudaGetSymbolAddress((void**)&Hb,  g_H);

    cudaFuncSetAttribute(k_tgemm<0, 128>, cudaFuncAttributeMaxDynamicSharedMemorySize, SMEM128);
    cudaFuncSetAttribute(k_tgemm<1, 128>, cudaFuncAttributeMaxDynamicSharedMemorySize, SMEM128);
    cudaFuncSetAttribute(k_tgemm<2, 64>,  cudaFuncAttributeMaxDynamicSharedMemorySize, SMEM64);
    cudaFuncSetAttribute(k_tgemm<3, 64>,  cudaFuncAttributeMaxDynamicSharedMemorySize, SMEM64);

    dim3 tb(32, 8);

    // 1) transpose x (B,C,L) -> yn (B,L,C)
    {
        dim3 grid(LSEQ / 32, DIM / 32, BATCH);
        k_transpose<<<grid, tb>>>(x, yn, DIM, LSEQ);
    }
    // 2) layernorm in place
    k_layernorm<<<BL * 32 / 256, 256>>>(yn, gamma, beta);
    // 3) xz = yn @ W_in^T
    {
        dim3 grid(XZW / 128, BL / 128);
        k_tgemm<0, 128><<<grid, 256, SMEM128>>>(yn, W_in, nullptr, nullptr, xz, BL, XZW, DIM);
    }
    // 4) conv + silu -> u
    k_conv_silu<<<(BL * DI) / 256, 256>>>(xz, conv_w, conv_b, u);
    // 5) proj = u @ W_xp^T
    k_proj<<<BL / 8, 256>>>(u, W_xp, proj);
    // 6) dt
    k_dt<<<BL, DI>>>(proj, W_dt, b_dt, dt);
    // 7) chunked selective scan (+fused gate) -> ym
    {
        dim3 grid(BATCH * (DI / 8), NCHUNK);
        k_scan_chunk<1><<<grid, 128>>>(dt, u, proj, A_log, Pb, he, nullptr, nullptr, nullptr, nullptr);
        k_scan_carry<<<SCANW / 256, 256>>>(Pb, he, Hb);
        k_scan_chunk<3><<<grid, 128>>>(dt, u, proj, A_log, nullptr, nullptr, Hb, ym, xz, Dv);
    }
    // 8) y2 = ym @ W_out^T + yn
    {
        dim3 grid(DIM / 64, BL / 128);
        k_tgemm<2, 64><<<grid, 256, SMEM64>>>(ym, W_out, nullptr, yn, y2, BL, DIM, DI);
    }
    // 9) hid = gelu(y2 @ W1^T + b1)
    {
        dim3 grid(HIDW / 128, BL / 128);
        k_tgemm<1, 128><<<grid, 256, SMEM128>>>(y2, W1, b1, nullptr, hid, BL, HIDW, DIM);
    }
    // 10) y3 = hid @ W2^T + b2 + y2
    {
        dim3 grid(DIM / 64, BL / 128);
        k_tgemm<3, 64><<<grid, 256, SMEM64>>>(hid, W2, b2, y2, y3, BL, DIM, HIDW);
    }
    // 11) transpose y3 (B,L,C) -> out (B,C,L)
    {
        dim3 grid(DIM / 32, LSEQ / 32, BATCH);
        k_transpose<<<grid, tb>>>(y3, out, LSEQ, DIM);
    }
}

// round 8
// speedup vs baseline: 2.0919x; 1.0678x over previous
#include <cuda_runtime.h>
#include <cuda_bf16.h>
#include <cuda_fp16.h>
#include <math.h>
#include <stdint.h>

// Problem constants
#define BATCH 2
#define DIM   256
#define HW    64
#define LSEQ  4096
#define BL    8192
#define DI    512
#define NST   16
#define RNK   16
#define XZW   1024
#define HIDW  1024

#define NCHUNK 64
#define CS     64
#define SCANW  16384

// ---------------- scratch ----------------------------------------------------
__device__ float g_yn  [(size_t)BL * DIM];
__device__ float g_xz  [(size_t)BL * XZW];
__device__ float g_u   [(size_t)BL * DI];
__device__ float g_proj[(size_t)BL * 48];
__device__ float g_dt  [(size_t)BL * DI];
__device__ float g_ym  [(size_t)BL * DI];
__device__ float g_y2  [(size_t)BL * DIM];
__device__ float g_hid [(size_t)BL * HIDW];
__device__ float g_y3  [(size_t)BL * DIM];
__device__ float g_P   [(size_t)NCHUNK * SCANW];
__device__ float g_he  [(size_t)NCHUNK * SCANW];
__device__ float g_H   [(size_t)NCHUNK * SCANW];

// ---------------- transpose --------------------------------------------------
__global__ void k_transpose(const float* __restrict__ in, float* __restrict__ out,
                            int D1, int D2) {
    __shared__ float tile[32][33];
    int b  = blockIdx.z;
    int i0 = blockIdx.y * 32;
    int j0 = blockIdx.x * 32;
    int tx = threadIdx.x, ty = threadIdx.y;
    const float* ip = in  + (size_t)b * D1 * D2;
    float*       op = out + (size_t)b * D1 * D2;
#pragma unroll
    for (int s = 0; s < 32; s += 8)
        tile[ty + s][tx] = ip[(size_t)(i0 + ty + s) * D2 + j0 + tx];
    __syncthreads();
#pragma unroll
    for (int s = 0; s < 32; s += 8)
        op[(size_t)(j0 + ty + s) * D1 + i0 + tx] = tile[tx][ty + s];
}

// ---------------- layernorm --------------------------------------------------
__global__ void k_layernorm(float* __restrict__ y,
                            const float* __restrict__ gamma,
                            const float* __restrict__ beta) {
    int gw   = (blockIdx.x * blockDim.x + threadIdx.x) >> 5;
    int lane = threadIdx.x & 31;
    if (gw >= BL) return;
    float* row = y + (size_t)gw * DIM;
    float v[8];
    float s = 0.f;
#pragma unroll
    for (int t = 0; t < 8; t++) { v[t] = row[lane + 32 * t]; s += v[t]; }
#pragma unroll
    for (int o = 16; o > 0; o >>= 1) s += __shfl_xor_sync(~0u, s, o);
    float mu = s * (1.f / DIM);
    float var = 0.f;
#pragma unroll
    for (int t = 0; t < 8; t++) { float d = v[t] - mu; var += d * d; }
#pragma unroll
    for (int o = 16; o > 0; o >>= 1) var += __shfl_xor_sync(~0u, var, o);
    float rstd = rsqrtf(var * (1.f / DIM) + 1e-5f);
#pragma unroll
    for (int t = 0; t < 8; t++) {
        int c = lane + 32 * t;
        row[c] = (v[t] - mu) * rstd * gamma[c] + beta[c];
    }
}

// ---------------- causal depthwise conv(4) + silu ----------------------------
__global__ void k_conv_silu(const float* __restrict__ xz,
                            const float* __restrict__ cw,
                            const float* __restrict__ cb,
                            float* __restrict__ u) {
    int i = blockIdx.x * blockDim.x + threadIdx.x;
    if (i >= BL * DI) return;
    int d    = i & (DI - 1);
    int lrow = i >> 9;
    int l    = lrow & (LSEQ - 1);
    float acc = cb[d];
#pragma unroll
    for (int k = 0; k < 4; k++) {
        int ll = l - 3 + k;
        if (ll >= 0)
            acc += cw[d * 4 + k] * xz[(size_t)(lrow - 3 + k) * XZW + d];
    }
    u[i] = acc / (1.f + __expf(-acc));
}

// ---------------- x-proj -----------------------------------------------------
__global__ void k_proj(const float* __restrict__ u,
                       const float* __restrict__ Wxp,
                       float* __restrict__ proj) {
    int gw   = (blockIdx.x * blockDim.x + threadIdx.x) >> 5;
    int lane = threadIdx.x & 31;
    if (gw >= BL) return;
    const float* ur = u + (size_t)gw * DI;
    float ureg[16];
#pragma unroll
    for (int t = 0; t < 16; t++) ureg[t] = ur[lane + 32 * t];
    for (int j = 0; j < 48; j++) {
        const float* w = Wxp + (size_t)j * DI;
        float s = 0.f;
#pragma unroll
        for (int t = 0; t < 16; t++) s += ureg[t] * w[lane + 32 * t];
#pragma unroll
        for (int o = 16; o > 0; o >>= 1) s += __shfl_xor_sync(~0u, s, o);
        if (lane == 0) proj[(size_t)gw * 48 + j] = s;
    }
}

// ---------------- dt = softplus(proj[:, :16] @ W_dt^T + b_dt) ----------------
// 16 rows per block; W_dt staged in smem once per block.
__global__ void __launch_bounds__(256) k_dt(
    const float* __restrict__ proj, const float* __restrict__ Wdt,
    const float* __restrict__ bdt, float* __restrict__ dt) {
    __shared__ float sw[DI * RNK];      // 32 KB
    __shared__ float sp[16][RNK];
    int tid = threadIdx.x;
    int i0  = blockIdx.x * 16;
    for (int idx = tid; idx < DI * RNK; idx += 256) sw[idx] = Wdt[idx];
    if (tid < 256) {
        int r = tid >> 4, k = tid & 15;
        sp[r][k] = proj[(size_t)(i0 + r) * 48 + k];
    }
    __syncthreads();
    int d = tid * 2;
    float w0[RNK], w1[RNK];
#pragma unroll
    for (int k = 0; k < RNK; k++) { w0[k] = sw[d * RNK + k]; w1[k] = sw[(d + 1) * RNK + k]; }
    float b0 = bdt[d], b1 = bdt[d + 1];
#pragma unroll 4
    for (int r = 0; r < 16; r++) {
        float s0 = b0, s1 = b1;
#pragma unroll
        for (int k = 0; k < RNK; k++) {
            float pv = sp[r][k];
            s0 += pv * w0[k];
            s1 += pv * w1[k];
        }
        float o0 = fmaxf(s0, 0.f) + log1pf(__expf(-fabsf(s0)));
        float o1 = fmaxf(s1, 0.f) + log1pf(__expf(-fabsf(s1)));
        *(float2*)(dt + (size_t)(i0 + r) * DI + d) = make_float2(o0, o1);
    }
}

// =============== chunked selective scan ======================================
template <int PASS>
__global__ void __launch_bounds__(128) k_scan_chunk(
    const float* __restrict__ dt, const float* __restrict__ u,
    const float* __restrict__ proj, const float* __restrict__ A_log,
    float* __restrict__ Pout, float* __restrict__ heout,
    const float* __restrict__ Hin, float* __restrict__ ys,
    const float* __restrict__ xz, const float* __restrict__ Dv) {
    __shared__ float sdt[CS * 8], su[CS * 8], sB[CS * 16], sC[CS * 16], sy[CS * 8];
    int blk = blockIdx.x;
    int b   = blk >> 6;
    int d0  = (blk & 63) * 8;
    int chunk = blockIdx.y;
    int tid  = threadIdx.x;
    int dloc = tid >> 4;
    int n    = tid & 15;
    int d    = d0 + dloc;
    float a = -__expf(A_log[d * NST + n]);
    size_t base = (size_t)b * LSEQ + (size_t)chunk * CS;

    for (int idx = tid; idx < CS * 8; idx += 128) {
        int j = idx >> 3, dd = idx & 7;
        size_t g = (base + j) * DI + d0 + dd;
        sdt[idx] = dt[g];
        su[idx]  = u[g];
    }
    for (int idx = tid; idx < CS * 16; idx += 128) {
        int j = idx >> 4, nn = idx & 15;
        size_t g = (base + j) * 48;
        sB[idx] = proj[g + 16 + nn];
        if (PASS == 3) sC[idx] = proj[g + 32 + nn];
    }
    __syncthreads();

    size_t sidx = (size_t)chunk * SCANW + (size_t)b * (DI * NST) + d * NST + n;

    if (PASS == 1) {
        float h = 0.f, Pr = 1.f;
#pragma unroll 8
        for (int j = 0; j < CS; j++) {
            float dtv = sdt[j * 8 + dloc];
            float dA  = __expf(dtv * a);
            h  = dA * h + (dtv * su[j * 8 + dloc]) * sB[j * 16 + n];
            Pr *= dA;
        }
        Pout[sidx] = Pr;
        heout[sidx] = h;
    } else {
        float h = Hin[sidx];
#pragma unroll 4
        for (int j = 0; j < CS; j++) {
            float dtv = sdt[j * 8 + dloc];
            float dA  = __expf(dtv * a);
            h = dA * h + (dtv * su[j * 8 + dloc]) * sB[j * 16 + n];
            float yv = h * sC[j * 16 + n];
            yv += __shfl_xor_sync(~0u, yv, 8);
            yv += __shfl_xor_sync(~0u, yv, 4);
            yv += __shfl_xor_sync(~0u, yv, 2);
            yv += __shfl_xor_sync(~0u, yv, 1);
            if (n == 0) sy[j * 8 + dloc] = yv;
        }
        __syncthreads();
        for (int idx = tid; idx < CS * 8; idx += 128) {
            int j = idx >> 3, dd = idx & 7;
            int dg = d0 + dd;
            float zv  = xz[(base + j) * XZW + DI + dg];
            float sil = zv / (1.f + __expf(-zv));
            ys[(base + j) * DI + dg] = (sy[idx] + su[idx] * Dv[dg]) * sil;
        }
    }
}

__global__ void k_scan_carry(const float* __restrict__ P,
                             const float* __restrict__ he,
                             float* __restrict__ H) {
    int tid = blockIdx.x * blockDim.x + threadIdx.x;
    if (tid >= SCANW) return;
    float Hc = 0.f;
#pragma unroll 8
    for (int c = 0; c < NCHUNK; c++) {
        size_t idx = (size_t)c * SCANW + tid;
        H[idx] = Hc;
        Hc = P[idx] * Hc + he[idx];
    }
}

// ================= FP16 tensor-core GEMM (m16n8k16, double-buffered) =========
__device__ __forceinline__ void mma_f16(float& c0, float& c1, float& c2, float& c3,
                                        uint32_t a0, uint32_t a1, uint32_t a2, uint32_t a3,
                                        uint32_t b0, uint32_t b1) {
    asm volatile(
        "mma.sync.aligned.m16n8k16.row.col.f32.f16.f16.f32 "
        "{%0,%1,%2,%3}, {%4,%5,%6,%7}, {%8,%9}, {%0,%1,%2,%3};"
        : "+f"(c0), "+f"(c1), "+f"(c2), "+f"(c3)
        : "r"(a0), "r"(a1), "r"(a2), "r"(a3), "r"(b0), "r"(b1));
}

__device__ __forceinline__ void ldsm4(uint32_t* r, uint32_t addr) {
    asm volatile("ldmatrix.sync.aligned.m8n8.x4.shared.b16 {%0,%1,%2,%3}, [%4];"
                 : "=r"(r[0]), "=r"(r[1]), "=r"(r[2]), "=r"(r[3]) : "r"(addr));
}

__device__ __forceinline__ uint4 pack8(float4 a, float4 b) {
    __half2 h0 = __floats2half2_rn(a.x, a.y);
    __half2 h1 = __floats2half2_rn(a.z, a.w);
    __half2 h2 = __floats2half2_rn(b.x, b.y);
    __half2 h3 = __floats2half2_rn(b.z, b.w);
    uint4 r;
    r.x = *(uint32_t*)&h0; r.y = *(uint32_t*)&h1;
    r.z = *(uint32_t*)&h2; r.w = *(uint32_t*)&h3;
    return r;
}

// C(M,N) = A(M,K) @ Bw(N,K)^T (+ epilogue). K%32==0, M%128==0, N%TN==0.
// Row stride 40 halves (80B): ldmatrix banks 20r mod 32 -> conflict-free.
// EPI: 0 none; 1 bias+gelu; 2 +resid; 3 bias+resid
template <int EPI, int TN>
__global__ void __launch_bounds__(256) k_hgemm(
    const float* __restrict__ A, const float* __restrict__ Bw,
    const float* __restrict__ bias, const float* __restrict__ resid,
    float* __restrict__ C, int M, int N, int K) {
    constexpr int WN   = TN / 4;
    constexpr int NI   = WN / 8;
    constexpr int NP   = NI / 2;
    constexpr int AH   = 128 * 40;            // halves per A buffer
    constexpr int BHH  = TN * 40;             // halves per B buffer
    constexpr int BUFH = AH + BHH;

    __shared__ __half sm[2 * BUFH];

    int tid  = threadIdx.x;
    int lane = tid & 31;
    int wid  = tid >> 5;
    int wm   = wid & 1;
    int wn   = wid >> 1;
    int grp  = lane >> 2;
    int l4   = lane & 3;
    int m8   = lane >> 3;
    int lr8  = lane & 7;

    int row0 = blockIdx.y * 128;
    int col0 = blockIdx.x * TN;

    // staging maps
    int ar = tid >> 1, ah = (tid & 1) * 16;                 // A: 16 halves/thread
    int br, bh;                                             // B
    if (TN == 128) { br = tid >> 1; bh = (tid & 1) * 16; }
    else           { br = tid >> 2; bh = (tid & 3) * 8;  }

    uint32_t a_base[4], b_base[NP];
#pragma unroll
    for (int mi = 0; mi < 4; mi++)
        a_base[mi] = (uint32_t)__cvta_generic_to_shared(
            &sm[(wm * 64 + mi * 16 + lr8 + 8 * (m8 & 1)) * 40 + (m8 >> 1) * 8]);
#pragma unroll
    for (int p = 0; p < NP; p++)
        b_base[p] = (uint32_t)__cvta_generic_to_shared(
            &sm[AH + (wn * WN + p * 16 + (m8 >> 1) * 8 + lr8) * 40 + (m8 & 1) * 8]);

    const uint32_t bufB = BUFH * 2;  // bytes per buffer

    float acc[4][NI][4];
#pragma unroll
    for (int mi = 0; mi < 4; mi++)
#pragma unroll
        for (int ni = 0; ni < NI; ni++)
#pragma unroll
            for (int t = 0; t < 4; t++) acc[mi][ni][t] = 0.f;

    // prologue: tile 0 -> buffer 0
    float4 ra[4], rb[4];
#pragma unroll
    for (int f = 0; f < 4; f++)
        ra[f] = *(const float4*)(A + (size_t)(row0 + ar) * K + ah + f * 4);
    if (TN == 128) {
#pragma unroll
        for (int f = 0; f < 4; f++)
            rb[f] = *(const float4*)(Bw + (size_t)(col0 + br) * K + bh + f * 4);
    } else {
#pragma unroll
        for (int f = 0; f < 2; f++)
            rb[f] = *(const float4*)(Bw + (size_t)(col0 + br) * K + bh + f * 4);
    }
    *(uint4*)&sm[ar * 40 + ah]     = pack8(ra[0], ra[1]);
    *(uint4*)&sm[ar * 40 + ah + 8] = pack8(ra[2], ra[3]);
    if (TN == 128) {
        *(uint4*)&sm[AH + br * 40 + bh]     = pack8(rb[0], rb[1]);
        *(uint4*)&sm[AH + br * 40 + bh + 8] = pack8(rb[2], rb[3]);
    } else {
        *(uint4*)&sm[AH + br * 40 + bh] = pack8(rb[0], rb[1]);
    }
    __syncthreads();

    int buf = 0;
    for (int kt = 0; kt < K; kt += 32) {
        bool more = (kt + 32) < K;
        if (more) {
#pragma unroll
            for (int f = 0; f < 4; f++)
                ra[f] = *(const float4*)(A + (size_t)(row0 + ar) * K + kt + 32 + ah + f * 4);
            if (TN == 128) {
#pragma unroll
                for (int f = 0; f < 4; f++)
                    rb[f] = *(const float4*)(Bw + (size_t)(col0 + br) * K + kt + 32 + bh + f * 4);
            } else {
#pragma unroll
                for (int f = 0; f < 2; f++)
                    rb[f] = *(const float4*)(Bw + (size_t)(col0 + br) * K + kt + 32 + bh + f * 4);
            }
        }

        uint32_t boff = buf * bufB;
#pragma unroll
        for (int ks = 0; ks < 2; ks++) {
            uint32_t af[4][4], bfr[NI][2];
#pragma unroll
            for (int mi = 0; mi < 4; mi++)
                ldsm4(af[mi], a_base[mi] + boff + ks * 32);
#pragma unroll
            for (int p = 0; p < NP; p++) {
                uint32_t bq[4];
                ldsm4(bq, b_base[p] + boff + ks * 32);
                bfr[2 * p][0]     = bq[0];
                bfr[2 * p][1]     = bq[1];
                bfr[2 * p + 1][0] = bq[2];
                bfr[2 * p + 1][1] = bq[3];
            }
#pragma unroll
            for (int mi = 0; mi < 4; mi++)
#pragma unroll
                for (int ni = 0; ni < NI; ni++)
                    mma_f16(acc[mi][ni][0], acc[mi][ni][1], acc[mi][ni][2], acc[mi][ni][3],
                            af[mi][0], af[mi][1], af[mi][2], af[mi][3],
                            bfr[ni][0], bfr[ni][1]);
        }

        if (more) {
            uint32_t w = (buf ^ 1) * BUFH;
            *(uint4*)&sm[w + ar * 40 + ah]     = pack8(ra[0], ra[1]);
            *(uint4*)&sm[w + ar * 40 + ah + 8] = pack8(ra[2], ra[3]);
            if (TN == 128) {
                *(uint4*)&sm[w + AH + br * 40 + bh]     = pack8(rb[0], rb[1]);
                *(uint4*)&sm[w + AH + br * 40 + bh + 8] = pack8(rb[2], rb[3]);
            } else {
                *(uint4*)&sm[w + AH + br * 40 + bh] = pack8(rb[0], rb[1]);
            }
        }
        __syncthreads();
        buf ^= 1;
    }

    // epilogue
#pragma unroll
    for (int mi = 0; mi < 4; mi++) {
#pragma unroll
        for (int ni = 0; ni < NI; ni++) {
            int r = row0 + wm * 64 + mi * 16 + grp;
            int c = col0 + wn * WN + ni * 8 + l4 * 2;
#pragma unroll
            for (int half = 0; half < 2; half++) {
                int rr = r + half * 8;
                float v0 = acc[mi][ni][half * 2 + 0];
                float v1 = acc[mi][ni][half * 2 + 1];
                if (EPI == 1) {
                    v0 += bias[c];     v1 += bias[c + 1];
                    v0 = 0.5f * v0 * (1.f + erff(v0 * 0.70710678118654752f));
                    v1 = 0.5f * v1 * (1.f + erff(v1 * 0.70710678118654752f));
                } else if (EPI == 2) {
                    const float2 rv = *(const float2*)(resid + (size_t)rr * N + c);
                    v0 += rv.x; v1 += rv.y;
                } else if (EPI == 3) {
                    const float2 rv = *(const float2*)(resid + (size_t)rr * N + c);
                    v0 += bias[c] + rv.x; v1 += bias[c + 1] + rv.y;
                }
                *(float2*)(C + (size_t)rr * N + c) = make_float2(v0, v1);
            }
        }
    }
}

// ---------------- launcher ---------------------------------------------------
extern "C" void kernel_launch(void* const* d_in, const int* in_sizes, int n_in,
                              void* d_out, int out_size) {
    const float* x      = (const float*)d_in[0];
    const float* gamma  = (const float*)d_in[1];
    const float* beta   = (const float*)d_in[2];
    const float* W_in   = (const float*)d_in[3];
    const float* conv_w = (const float*)d_in[4];
    const float* conv_b = (const float*)d_in[5];
    const float* W_xp   = (const float*)d_in[6];
    const float* W_dt   = (const float*)d_in[7];
    const float* b_dt   = (const float*)d_in[8];
    const float* A_log  = (const float*)d_in[9];
    const float* Dv     = (const float*)d_in[10];
    const float* W_out  = (const float*)d_in[11];
    const float* W1     = (const float*)d_in[12];
    const float* b1     = (const float*)d_in[13];
    const float* W2     = (const float*)d_in[14];
    const float* b2     = (const float*)d_in[15];
    float* out = (float*)d_out;

    float *yn, *xz, *u, *proj, *dt, *ym, *y2, *hid, *y3, *Pb, *he, *Hb;
    cudaGetSymbolAddress((void**)&yn,  g_yn);
    cudaGetSymbolAddress((void**)&xz,  g_xz);
    cudaGetSymbolAddress((void**)&u,   g_u);
    cudaGetSymbolAddress((void**)&proj,g_proj);
    cudaGetSymbolAddress((void**)&dt,  g_dt);
    cudaGetSymbolAddress((void**)&ym,  g_ym);
    cudaGetSymbolAddress((void**)&y2,  g_y2);
    cudaGetSymbolAddress((void**)&hid, g_hid);
    cudaGetSymbolAddress((void**)&y3,  g_y3);
    cudaGetSymbolAddress((void**)&Pb,  g_P);
    cudaGetSymbolAddress((void**)&he,  g_he);
    cudaGetSymbolAddress((void**)&Hb,  g_H);

    dim3 tb(32, 8);

    // 1) transpose x (B,C,L) -> yn (B,L,C)
    {
        dim3 grid(LSEQ / 32, DIM / 32, BATCH);
        k_transpose<<<grid, tb>>>(x, yn, DIM, LSEQ);
    }
    // 2) layernorm in place
    k_layernorm<<<BL * 32 / 256, 256>>>(yn, gamma, beta);
    // 3) xz = yn @ W_in^T
    {
        dim3 grid(XZW / 128, BL / 128);
        k_hgemm<0, 128><<<grid, 256>>>(yn, W_in, nullptr, nullptr, xz, BL, XZW, DIM);
    }
    // 4) conv + silu -> u
    k_conv_silu<<<(BL * DI) / 256, 256>>>(xz, conv_w, conv_b, u);
    // 5) proj = u @ W_xp^T
    k_proj<<<BL / 8, 256>>>(u, W_xp, proj);
    // 6) dt (smem-staged W_dt)
    k_dt<<<BL / 16, 256>>>(proj, W_dt, b_dt, dt);
    // 7) chunked selective scan (+fused gate) -> ym
    {
        dim3 grid(BATCH * (DI / 8), NCHUNK);
        k_scan_chunk<1><<<grid, 128>>>(dt, u, proj, A_log, Pb, he, nullptr, nullptr, nullptr, nullptr);
        k_scan_carry<<<SCANW / 256, 256>>>(Pb, he, Hb);
        k_scan_chunk<3><<<grid, 128>>>(dt, u, proj, A_log, nullptr, nullptr, Hb, ym, xz, Dv);
    }
    // 8) y2 = ym @ W_out^T + yn
    {
        dim3 grid(DIM / 64, BL / 128);
        k_hgemm<2, 64><<<grid, 256>>>(ym, W_out, nullptr, yn, y2, BL, DIM, DI);
    }
    // 9) hid = gelu(y2 @ W1^T + b1)
    {
        dim3 grid(HIDW / 128, BL / 128);
        k_hgemm<1, 128><<<grid, 256>>>(y2, W1, b1, nullptr, hid, BL, HIDW, DIM);
    }
    // 10) y3 = hid @ W2^T + b2 + y2
    {
        dim3 grid(DIM / 64, BL / 128);
        k_hgemm<3, 64><<<grid, 256>>>(hid, W2, b2, y2, y3, BL, DIM, HIDW);
    }
    // 11) transpose y3 (B,L,C) -> out (B,C,L)
    {
        dim3 grid(DIM / 32, LSEQ / 32, BATCH);
        k_transpose<<<grid, tb>>>(y3, out, LSEQ, DIM);
    }
}

// round 9
// speedup vs baseline: 2.1451x; 1.0254x over previous
#include <cuda_runtime.h>
#include <cuda_bf16.h>
#include <cuda_fp16.h>
#include <math.h>
#include <stdint.h>

// Problem constants
#define BATCH 2
#define DIM   256
#define HW    64
#define LSEQ  4096
#define BL    8192
#define DI    512
#define NST   16
#define RNK   16
#define XZW   1024
#define HIDW  1024

#define NCHUNK 64
#define CS     64
#define SCANW  16384

// ---------------- scratch ----------------------------------------------------
__device__ float  g_yn  [(size_t)BL * DIM];
__device__ __half g_xz  [(size_t)BL * XZW];    // fp16 (xm | z)
__device__ float  g_u   [(size_t)BL * DI];
__device__ float  g_proj[(size_t)BL * 48];
__device__ float  g_dt  [(size_t)BL * DI];
__device__ float  g_ym  [(size_t)BL * DI];
__device__ float  g_y2  [(size_t)BL * DIM];
__device__ __half g_hid [(size_t)BL * HIDW];   // fp16
__device__ float  g_y3  [(size_t)BL * DIM];
__device__ float  g_P   [(size_t)NCHUNK * SCANW];
__device__ float  g_he  [(size_t)NCHUNK * SCANW];
__device__ float  g_H   [(size_t)NCHUNK * SCANW];

// ---------------- fused transpose + layernorm --------------------------------
// x (B, C=256, L) -> yn (B, L, C) with per-row LN, single pass.
__global__ void __launch_bounds__(256) k_transpose_ln(
    const float* __restrict__ x, const float* __restrict__ gamma,
    const float* __restrict__ beta, float* __restrict__ yn) {
    __shared__ float tile[DIM][33];
    int b  = blockIdx.y;
    int l0 = blockIdx.x * 32;
    int tx = threadIdx.x & 31;   // l offset
    int tg = threadIdx.x >> 5;   // 0..7
    const float* xp = x + (size_t)b * DIM * LSEQ;
#pragma unroll 4
    for (int c = tg; c < DIM; c += 8)
        tile[c][tx] = xp[(size_t)c * LSEQ + l0 + tx];
    __syncthreads();
    // each warp handles 4 rows (l values)
    int lane = tx;
#pragma unroll
    for (int r = 0; r < 4; r++) {
        int l = tg * 4 + r;
        float v[8];
        float s = 0.f;
#pragma unroll
        for (int t = 0; t < 8; t++) { v[t] = tile[lane + 32 * t][l]; s += v[t]; }
#pragma unroll
        for (int o = 16; o > 0; o >>= 1) s += __shfl_xor_sync(~0u, s, o);
        float mu = s * (1.f / DIM);
        float var = 0.f;
#pragma unroll
        for (int t = 0; t < 8; t++) { float d = v[t] - mu; var += d * d; }
#pragma unroll
        for (int o = 16; o > 0; o >>= 1) var += __shfl_xor_sync(~0u, var, o);
        float rstd = rsqrtf(var * (1.f / DIM) + 1e-5f);
        float* row = yn + ((size_t)b * LSEQ + l0 + l) * DIM;
#pragma unroll
        for (int t = 0; t < 8; t++) {
            int c = lane + 32 * t;
            row[c] = (v[t] - mu) * rstd * gamma[c] + beta[c];
        }
    }
}

// ---------------- final transpose --------------------------------------------
__global__ void k_transpose(const float* __restrict__ in, float* __restrict__ out,
                            int D1, int D2) {
    __shared__ float tile[32][33];
    int b  = blockIdx.z;
    int i0 = blockIdx.y * 32;
    int j0 = blockIdx.x * 32;
    int tx = threadIdx.x, ty = threadIdx.y;
    const float* ip = in  + (size_t)b * D1 * D2;
    float*       op = out + (size_t)b * D1 * D2;
#pragma unroll
    for (int s = 0; s < 32; s += 8)
        tile[ty + s][tx] = ip[(size_t)(i0 + ty + s) * D2 + j0 + tx];
    __syncthreads();
#pragma unroll
    for (int s = 0; s < 32; s += 8)
        op[(size_t)(j0 + ty + s) * D1 + i0 + tx] = tile[tx][ty + s];
}

// ---------------- causal depthwise conv(4) + silu (fp16 xz input) ------------
__global__ void k_conv_silu(const __half* __restrict__ xz,
                            const float* __restrict__ cw,
                            const float* __restrict__ cb,
                            float* __restrict__ u) {
    int i = blockIdx.x * blockDim.x + threadIdx.x;
    if (i >= BL * DI) return;
    int d    = i & (DI - 1);
    int lrow = i >> 9;
    int l    = lrow & (LSEQ - 1);
    float acc = cb[d];
#pragma unroll
    for (int k = 0; k < 4; k++) {
        int ll = l - 3 + k;
        if (ll >= 0)
            acc += cw[d * 4 + k] * __half2float(xz[(size_t)(lrow - 3 + k) * XZW + d]);
    }
    u[i] = acc / (1.f + __expf(-acc));
}

// ---------------- x-proj -----------------------------------------------------
__global__ void k_proj(const float* __restrict__ u,
                       const float* __restrict__ Wxp,
                       float* __restrict__ proj) {
    int gw   = (blockIdx.x * blockDim.x + threadIdx.x) >> 5;
    int lane = threadIdx.x & 31;
    if (gw >= BL) return;
    const float* ur = u + (size_t)gw * DI;
    float ureg[16];
#pragma unroll
    for (int t = 0; t < 16; t++) ureg[t] = ur[lane + 32 * t];
    for (int j = 0; j < 48; j++) {
        const float* w = Wxp + (size_t)j * DI;
        float s = 0.f;
#pragma unroll
        for (int t = 0; t < 16; t++) s += ureg[t] * w[lane + 32 * t];
#pragma unroll
        for (int o = 16; o > 0; o >>= 1) s += __shfl_xor_sync(~0u, s, o);
        if (lane == 0) proj[(size_t)gw * 48 + j] = s;
    }
}

// ---------------- dt ----------------------------------------------------------
__global__ void __launch_bounds__(256) k_dt(
    const float* __restrict__ proj, const float* __restrict__ Wdt,
    const float* __restrict__ bdt, float* __restrict__ dt) {
    __shared__ float sw[DI * RNK];
    __shared__ float sp[16][RNK];
    int tid = threadIdx.x;
    int i0  = blockIdx.x * 16;
    for (int idx = tid; idx < DI * RNK; idx += 256) sw[idx] = Wdt[idx];
    if (tid < 256) {
        int r = tid >> 4, k = tid & 15;
        sp[r][k] = proj[(size_t)(i0 + r) * 48 + k];
    }
    __syncthreads();
    int d = tid * 2;
    float w0[RNK], w1[RNK];
#pragma unroll
    for (int k = 0; k < RNK; k++) { w0[k] = sw[d * RNK + k]; w1[k] = sw[(d + 1) * RNK + k]; }
    float b0 = bdt[d], b1 = bdt[d + 1];
#pragma unroll 4
    for (int r = 0; r < 16; r++) {
        float s0 = b0, s1 = b1;
#pragma unroll
        for (int k = 0; k < RNK; k++) {
            float pv = sp[r][k];
            s0 += pv * w0[k];
            s1 += pv * w1[k];
        }
        float o0 = fmaxf(s0, 0.f) + log1pf(__expf(-fabsf(s0)));
        float o1 = fmaxf(s1, 0.f) + log1pf(__expf(-fabsf(s1)));
        *(float2*)(dt + (size_t)(i0 + r) * DI + d) = make_float2(o0, o1);
    }
}

// =============== chunked selective scan ======================================
template <int PASS>
__global__ void __launch_bounds__(128) k_scan_chunk(
    const float* __restrict__ dt, const float* __restrict__ u,
    const float* __restrict__ proj, const float* __restrict__ A_log,
    float* __restrict__ Pout, float* __restrict__ heout,
    const float* __restrict__ Hin, float* __restrict__ ys,
    const __half* __restrict__ xz, const float* __restrict__ Dv) {
    __shared__ float sdt[CS * 8], su[CS * 8], sB[CS * 16], sC[CS * 16], sy[CS * 8];
    int blk = blockIdx.x;
    int b   = blk >> 6;
    int d0  = (blk & 63) * 8;
    int chunk = blockIdx.y;
    int tid  = threadIdx.x;
    int dloc = tid >> 4;
    int n    = tid & 15;
    int d    = d0 + dloc;
    float a = -__expf(A_log[d * NST + n]);
    size_t base = (size_t)b * LSEQ + (size_t)chunk * CS;

    for (int idx = tid; idx < CS * 8; idx += 128) {
        int j = idx >> 3, dd = idx & 7;
        size_t g = (base + j) * DI + d0 + dd;
        sdt[idx] = dt[g];
        su[idx]  = u[g];
    }
    for (int idx = tid; idx < CS * 16; idx += 128) {
        int j = idx >> 4, nn = idx & 15;
        size_t g = (base + j) * 48;
        sB[idx] = proj[g + 16 + nn];
        if (PASS == 3) sC[idx] = proj[g + 32 + nn];
    }
    __syncthreads();

    size_t sidx = (size_t)chunk * SCANW + (size_t)b * (DI * NST) + d * NST + n;

    if (PASS == 1) {
        float h = 0.f, Pr = 1.f;
#pragma unroll 8
        for (int j = 0; j < CS; j++) {
            float dtv = sdt[j * 8 + dloc];
            float dA  = __expf(dtv * a);
            h  = dA * h + (dtv * su[j * 8 + dloc]) * sB[j * 16 + n];
            Pr *= dA;
        }
        Pout[sidx] = Pr;
        heout[sidx] = h;
    } else {
        float h = Hin[sidx];
#pragma unroll 4
        for (int j = 0; j < CS; j++) {
            float dtv = sdt[j * 8 + dloc];
            float dA  = __expf(dtv * a);
            h = dA * h + (dtv * su[j * 8 + dloc]) * sB[j * 16 + n];
            float yv = h * sC[j * 16 + n];
            yv += __shfl_xor_sync(~0u, yv, 8);
            yv += __shfl_xor_sync(~0u, yv, 4);
            yv += __shfl_xor_sync(~0u, yv, 2);
            yv += __shfl_xor_sync(~0u, yv, 1);
            if (n == 0) sy[j * 8 + dloc] = yv;
        }
        __syncthreads();
        for (int idx = tid; idx < CS * 8; idx += 128) {
            int j = idx >> 3, dd = idx & 7;
            int dg = d0 + dd;
            float zv  = __half2float(xz[(base + j) * XZW + DI + dg]);
            float sil = zv / (1.f + __expf(-zv));
            ys[(base + j) * DI + dg] = (sy[idx] + su[idx] * Dv[dg]) * sil;
        }
    }
}

__global__ void k_scan_carry(const float* __restrict__ P,
                             const float* __restrict__ he,
                             float* __restrict__ H) {
    int tid = blockIdx.x * blockDim.x + threadIdx.x;
    if (tid >= SCANW) return;
    float Hc = 0.f;
#pragma unroll 8
    for (int c = 0; c < NCHUNK; c++) {
        size_t idx = (size_t)c * SCANW + tid;
        H[idx] = Hc;
        Hc = P[idx] * Hc + he[idx];
    }
}

// ================= FP16 tensor-core GEMM =====================================
__device__ __forceinline__ void mma_f16(float& c0, float& c1, float& c2, float& c3,
                                        uint32_t a0, uint32_t a1, uint32_t a2, uint32_t a3,
                                        uint32_t b0, uint32_t b1) {
    asm volatile(
        "mma.sync.aligned.m16n8k16.row.col.f32.f16.f16.f32 "
        "{%0,%1,%2,%3}, {%4,%5,%6,%7}, {%8,%9}, {%0,%1,%2,%3};"
        : "+f"(c0), "+f"(c1), "+f"(c2), "+f"(c3)
        : "r"(a0), "r"(a1), "r"(a2), "r"(a3), "r"(b0), "r"(b1));
}

__device__ __forceinline__ void ldsm4(uint32_t* r, uint32_t addr) {
    asm volatile("ldmatrix.sync.aligned.m8n8.x4.shared.b16 {%0,%1,%2,%3}, [%4];"
                 : "=r"(r[0]), "=r"(r[1]), "=r"(r[2]), "=r"(r[3]) : "r"(addr));
}

__device__ __forceinline__ uint4 pack8(float4 a, float4 b) {
    __half2 h0 = __floats2half2_rn(a.x, a.y);
    __half2 h1 = __floats2half2_rn(a.z, a.w);
    __half2 h2 = __floats2half2_rn(b.x, b.y);
    __half2 h3 = __floats2half2_rn(b.z, b.w);
    uint4 r;
    r.x = *(uint32_t*)&h0; r.y = *(uint32_t*)&h1;
    r.z = *(uint32_t*)&h2; r.w = *(uint32_t*)&h3;
    return r;
}

// C(M,N) = A(M,K) @ Bw(N,K)^T (+ epilogue). Row stride 40 halves.
// EPI: 0 none; 1 bias+gelu; 2 +resid; 3 bias+resid
// AH16: A operand stored fp16 in gmem. OH16: output stored fp16.
template <int EPI, int TN, bool AH16, bool OH16>
__global__ void __launch_bounds__(256) k_hgemm(
    const void* __restrict__ Av, const float* __restrict__ Bw,
    const float* __restrict__ bias, const float* __restrict__ resid,
    void* __restrict__ Cv, int M, int N, int K) {
    constexpr int WN   = TN / 4;
    constexpr int NI   = WN / 8;
    constexpr int NP   = NI / 2;
    constexpr int AHW  = 128 * 40;
    constexpr int BHH  = TN * 40;
    constexpr int BUFH = AHW + BHH;

    __shared__ __half sm[2 * BUFH];

    int tid  = threadIdx.x;
    int lane = tid & 31;
    int wid  = tid >> 5;
    int wm   = wid & 1;
    int wn   = wid >> 1;
    int grp  = lane >> 2;
    int l4   = lane & 3;
    int m8   = lane >> 3;
    int lr8  = lane & 7;

    int row0 = blockIdx.y * 128;
    int col0 = blockIdx.x * TN;

    int ar = tid >> 1, ah = (tid & 1) * 16;
    int br, bh;
    if (TN == 128) { br = tid >> 1; bh = (tid & 1) * 16; }
    else           { br = tid >> 2; bh = (tid & 3) * 8;  }

    uint32_t a_base[4], b_base[NP];
#pragma unroll
    for (int mi = 0; mi < 4; mi++)
        a_base[mi] = (uint32_t)__cvta_generic_to_shared(
            &sm[(wm * 64 + mi * 16 + lr8 + 8 * (m8 & 1)) * 40 + (m8 >> 1) * 8]);
#pragma unroll
    for (int p = 0; p < NP; p++)
        b_base[p] = (uint32_t)__cvta_generic_to_shared(
            &sm[AHW + (wn * WN + p * 16 + (m8 >> 1) * 8 + lr8) * 40 + (m8 & 1) * 8]);

    const uint32_t bufB = BUFH * 2;

    float acc[4][NI][4];
#pragma unroll
    for (int mi = 0; mi < 4; mi++)
#pragma unroll
        for (int ni = 0; ni < NI; ni++)
#pragma unroll
            for (int t = 0; t < 4; t++) acc[mi][ni][t] = 0.f;

    const float*  Af = (const float*)Av;
    const __half* Ah = (const __half*)Av;

    float4 ra[4], rb[4];
    uint4  rah[2];

    // prologue loads (tile 0)
    if (AH16) {
        rah[0] = *(const uint4*)(Ah + (size_t)(row0 + ar) * K + ah);
        rah[1] = *(const uint4*)(Ah + (size_t)(row0 + ar) * K + ah + 8);
    } else {
#pragma unroll
        for (int f = 0; f < 4; f++)
            ra[f] = *(const float4*)(Af + (size_t)(row0 + ar) * K + ah + f * 4);
    }
    if (TN == 128) {
#pragma unroll
        for (int f = 0; f < 4; f++)
            rb[f] = *(const float4*)(Bw + (size_t)(col0 + br) * K + bh + f * 4);
    } else {
#pragma unroll
        for (int f = 0; f < 2; f++)
            rb[f] = *(const float4*)(Bw + (size_t)(col0 + br) * K + bh + f * 4);
    }
    // stage tile 0 -> buffer 0
    if (AH16) {
        *(uint4*)&sm[ar * 40 + ah]     = rah[0];
        *(uint4*)&sm[ar * 40 + ah + 8] = rah[1];
    } else {
        *(uint4*)&sm[ar * 40 + ah]     = pack8(ra[0], ra[1]);
        *(uint4*)&sm[ar * 40 + ah + 8] = pack8(ra[2], ra[3]);
    }
    if (TN == 128) {
        *(uint4*)&sm[AHW + br * 40 + bh]     = pack8(rb[0], rb[1]);
        *(uint4*)&sm[AHW + br * 40 + bh + 8] = pack8(rb[2], rb[3]);
    } else {
        *(uint4*)&sm[AHW + br * 40 + bh] = pack8(rb[0], rb[1]);
    }
    __syncthreads();

    int buf = 0;
    for (int kt = 0; kt < K; kt += 32) {
        bool more = (kt + 32) < K;
        if (more) {
            if (AH16) {
                rah[0] = *(const uint4*)(Ah + (size_t)(row0 + ar) * K + kt + 32 + ah);
                rah[1] = *(const uint4*)(Ah + (size_t)(row0 + ar) * K + kt + 32 + ah + 8);
            } else {
#pragma unroll
                for (int f = 0; f < 4; f++)
                    ra[f] = *(const float4*)(Af + (size_t)(row0 + ar) * K + kt + 32 + ah + f * 4);
            }
            if (TN == 128) {
#pragma unroll
                for (int f = 0; f < 4; f++)
                    rb[f] = *(const float4*)(Bw + (size_t)(col0 + br) * K + kt + 32 + bh + f * 4);
            } else {
#pragma unroll
                for (int f = 0; f < 2; f++)
                    rb[f] = *(const float4*)(Bw + (size_t)(col0 + br) * K + kt + 32 + bh + f * 4);
            }
        }

        uint32_t boff = buf * bufB;
#pragma unroll
        for (int ks = 0; ks < 2; ks++) {
            uint32_t af[4][4], bfr[NI][2];
#pragma unroll
            for (int mi = 0; mi < 4; mi++)
                ldsm4(af[mi], a_base[mi] + boff + ks * 32);
#pragma unroll
            for (int p = 0; p < NP; p++) {
                uint32_t bq[4];
                ldsm4(bq, b_base[p] + boff + ks * 32);
                bfr[2 * p][0]     = bq[0];
                bfr[2 * p][1]     = bq[1];
                bfr[2 * p + 1][0] = bq[2];
                bfr[2 * p + 1][1] = bq[3];
            }
#pragma unroll
            for (int mi = 0; mi < 4; mi++)
#pragma unroll
                for (int ni = 0; ni < NI; ni++)
                    mma_f16(acc[mi][ni][0], acc[mi][ni][1], acc[mi][ni][2], acc[mi][ni][3],
                            af[mi][0], af[mi][1], af[mi][2], af[mi][3],
                            bfr[ni][0], bfr[ni][1]);
        }

        if (more) {
            uint32_t w = (buf ^ 1) * BUFH;
            if (AH16) {
                *(uint4*)&sm[w + ar * 40 + ah]     = rah[0];
                *(uint4*)&sm[w + ar * 40 + ah + 8] = rah[1];
            } else {
                *(uint4*)&sm[w + ar * 40 + ah]     = pack8(ra[0], ra[1]);
                *(uint4*)&sm[w + ar * 40 + ah + 8] = pack8(ra[2], ra[3]);
            }
            if (TN == 128) {
                *(uint4*)&sm[w + AHW + br * 40 + bh]     = pack8(rb[0], rb[1]);
                *(uint4*)&sm[w + AHW + br * 40 + bh + 8] = pack8(rb[2], rb[3]);
            } else {
                *(uint4*)&sm[w + AHW + br * 40 + bh] = pack8(rb[0], rb[1]);
            }
        }
        __syncthreads();
        buf ^= 1;
    }

    float*  Cf = (float*)Cv;
    __half* Ch = (__half*)Cv;

#pragma unroll
    for (int mi = 0; mi < 4; mi++) {
#pragma unroll
        for (int ni = 0; ni < NI; ni++) {
            int r = row0 + wm * 64 + mi * 16 + grp;
            int c = col0 + wn * WN + ni * 8 + l4 * 2;
#pragma unroll
            for (int half = 0; half < 2; half++) {
                int rr = r + half * 8;
                float v0 = acc[mi][ni][half * 2 + 0];
                float v1 = acc[mi][ni][half * 2 + 1];
                if (EPI == 1) {
                    v0 += bias[c];     v1 += bias[c + 1];
                    v0 = 0.5f * v0 * (1.f + erff(v0 * 0.70710678118654752f));
                    v1 = 0.5f * v1 * (1.f + erff(v1 * 0.70710678118654752f));
                } else if (EPI == 2) {
                    const float2 rv = *(const float2*)(resid + (size_t)rr * N + c);
                    v0 += rv.x; v1 += rv.y;
                } else if (EPI == 3) {
                    const float2 rv = *(const float2*)(resid + (size_t)rr * N + c);
                    v0 += bias[c] + rv.x; v1 += bias[c + 1] + rv.y;
                }
                if (OH16) {
                    __half2 hv = __floats2half2_rn(v0, v1);
                    *(__half2*)(Ch + (size_t)rr * N + c) = hv;
                } else {
                    *(float2*)(Cf + (size_t)rr * N + c) = make_float2(v0, v1);
                }
            }
        }
    }
}

// ---------------- launcher ---------------------------------------------------
extern "C" void kernel_launch(void* const* d_in, const int* in_sizes, int n_in,
                              void* d_out, int out_size) {
    const float* x      = (const float*)d_in[0];
    const float* gamma  = (const float*)d_in[1];
    const float* beta   = (const float*)d_in[2];
    const float* W_in   = (const float*)d_in[3];
    const float* conv_w = (const float*)d_in[4];
    const float* conv_b = (const float*)d_in[5];
    const float* W_xp   = (const float*)d_in[6];
    const float* W_dt   = (const float*)d_in[7];
    const float* b_dt   = (const float*)d_in[8];
    const float* A_log  = (const float*)d_in[9];
    const float* Dv     = (const float*)d_in[10];
    const float* W_out  = (const float*)d_in[11];
    const float* W1     = (const float*)d_in[12];
    const float* b1     = (const float*)d_in[13];
    const float* W2     = (const float*)d_in[14];
    const float* b2     = (const float*)d_in[15];
    float* out = (float*)d_out;

    float *yn, *u, *proj, *dt, *ym, *y2, *y3, *Pb, *he, *Hb;
    __half *xz, *hid;
    cudaGetSymbolAddress((void**)&yn,  g_yn);
    cudaGetSymbolAddress((void**)&xz,  g_xz);
    cudaGetSymbolAddress((void**)&u,   g_u);
    cudaGetSymbolAddress((void**)&proj,g_proj);
    cudaGetSymbolAddress((void**)&dt,  g_dt);
    cudaGetSymbolAddress((void**)&ym,  g_ym);
    cudaGetSymbolAddress((void**)&y2,  g_y2);
    cudaGetSymbolAddress((void**)&hid, g_hid);
    cudaGetSymbolAddress((void**)&y3,  g_y3);
    cudaGetSymbolAddress((void**)&Pb,  g_P);
    cudaGetSymbolAddress((void**)&he,  g_he);
    cudaGetSymbolAddress((void**)&Hb,  g_H);

    // 1) fused transpose + layernorm -> yn
    {
        dim3 grid(LSEQ / 32, BATCH);
        k_transpose_ln<<<grid, 256>>>(x, gamma, beta, yn);
    }
    // 2) xz = yn @ W_in^T (fp16 out)
    {
        dim3 grid(XZW / 128, BL / 128);
        k_hgemm<0, 128, false, true><<<grid, 256>>>(yn, W_in, nullptr, nullptr, xz, BL, XZW, DIM);
    }
    // 3) conv + silu -> u
    k_conv_silu<<<(BL * DI) / 256, 256>>>(xz, conv_w, conv_b, u);
    // 4) proj = u @ W_xp^T
    k_proj<<<BL / 8, 256>>>(u, W_xp, proj);
    // 5) dt
    k_dt<<<BL / 16, 256>>>(proj, W_dt, b_dt, dt);
    // 6) chunked selective scan (+fused gate) -> ym
    {
        dim3 grid(BATCH * (DI / 8), NCHUNK);
        k_scan_chunk<1><<<grid, 128>>>(dt, u, proj, A_log, Pb, he, nullptr, nullptr, nullptr, nullptr);
        k_scan_carry<<<SCANW / 256, 256>>>(Pb, he, Hb);
        k_scan_chunk<3><<<grid, 128>>>(dt, u, proj, A_log, nullptr, nullptr, Hb, ym, xz, Dv);
    }
    // 7) y2 = ym @ W_out^T + yn
    {
        dim3 grid(DIM / 64, BL / 128);
        k_hgemm<2, 64, false, false><<<grid, 256>>>(ym, W_out, nullptr, yn, y2, BL, DIM, DI);
    }
    // 8) hid = gelu(y2 @ W1^T + b1) (fp16 out)
    {
        dim3 grid(HIDW / 128, BL / 128);
        k_hgemm<1, 128, false, true><<<grid, 256>>>(y2, W1, b1, nullptr, hid, BL, HIDW, DIM);
    }
    // 9) y3 = hid @ W2^T + b2 + y2 (fp16 A)
    {
        dim3 grid(DIM / 64, BL / 128);
        k_hgemm<3, 64, true, false><<<grid, 256>>>(hid, W2, b2, y2, y3, BL, DIM, HIDW);
    }
    // 10) transpose y3 (B,L,C) -> out (B,C,L)
    {
        dim3 tb(32, 8);
        dim3 grid(DIM / 32, LSEQ / 32, BATCH);
        k_transpose<<<grid, tb>>>(y3, out, LSEQ, DIM);
    }
}

// round 10
// speedup vs baseline: 2.4096x; 1.1233x over previous
#include <cuda_runtime.h>
#include <cuda_bf16.h>
#include <cuda_fp16.h>
#include <math.h>
#include <stdint.h>

// Problem constants
#define BATCH 2
#define DIM   256
#define HW    64
#define LSEQ  4096
#define BL    8192
#define DI    512
#define NST   16
#define RNK   16
#define XZW   1024
#define HIDW  1024
#define PROJW 64            // padded proj row stride (48 real cols)

#define NCHUNK 64
#define CS     64
#define SCANW  16384

// ---------------- scratch ----------------------------------------------------
__device__ float  g_yn  [(size_t)BL * DIM];
__device__ __half g_xz  [(size_t)BL * XZW];    // fp16 (xm | z)
__device__ float  g_u   [(size_t)BL * DI];
__device__ float  g_proj[(size_t)BL * PROJW];  // dt_raw(16)|B(16)|C(16)|pad(16)
__device__ float  g_wxp [(size_t)PROJW * DI];  // padded W_xp (64 x 512)
__device__ float  g_dt  [(size_t)BL * DI];
__device__ float  g_ym  [(size_t)BL * DI];
__device__ float  g_y2  [(size_t)BL * DIM];
__device__ __half g_hid [(size_t)BL * HIDW];   // fp16
__device__ float  g_y3  [(size_t)BL * DIM];
__device__ float  g_P   [(size_t)NCHUNK * SCANW];
__device__ float  g_he  [(size_t)NCHUNK * SCANW];
__device__ float  g_H   [(size_t)NCHUNK * SCANW];

// ---------------- pad W_xp (48x512) -> g_wxp (64x512, zero-padded) -----------
__global__ void k_padw(const float* __restrict__ Wxp, float* __restrict__ wp) {
    int i = blockIdx.x * blockDim.x + threadIdx.x;   // 0 .. 64*512-1
    int r = i >> 9;
    wp[i] = (r < 48) ? Wxp[i] : 0.f;
}

// ---------------- fused transpose + layernorm --------------------------------
__global__ void __launch_bounds__(256) k_transpose_ln(
    const float* __restrict__ x, const float* __restrict__ gamma,
    const float* __restrict__ beta, float* __restrict__ yn) {
    __shared__ float tile[DIM][33];
    int b  = blockIdx.y;
    int l0 = blockIdx.x * 32;
    int tx = threadIdx.x & 31;
    int tg = threadIdx.x >> 5;
    const float* xp = x + (size_t)b * DIM * LSEQ;
#pragma unroll 4
    for (int c = tg; c < DIM; c += 8)
        tile[c][tx] = xp[(size_t)c * LSEQ + l0 + tx];
    __syncthreads();
    int lane = tx;
#pragma unroll
    for (int r = 0; r < 4; r++) {
        int l = tg * 4 + r;
        float v[8];
        float s = 0.f;
#pragma unroll
        for (int t = 0; t < 8; t++) { v[t] = tile[lane + 32 * t][l]; s += v[t]; }
#pragma unroll
        for (int o = 16; o > 0; o >>= 1) s += __shfl_xor_sync(~0u, s, o);
        float mu = s * (1.f / DIM);
        float var = 0.f;
#pragma unroll
        for (int t = 0; t < 8; t++) { float d = v[t] - mu; var += d * d; }
#pragma unroll
        for (int o = 16; o > 0; o >>= 1) var += __shfl_xor_sync(~0u, var, o);
        float rstd = rsqrtf(var * (1.f / DIM) + 1e-5f);
        float* row = yn + ((size_t)b * LSEQ + l0 + l) * DIM;
#pragma unroll
        for (int t = 0; t < 8; t++) {
            int c = lane + 32 * t;
            row[c] = (v[t] - mu) * rstd * gamma[c] + beta[c];
        }
    }
}

// ---------------- final transpose --------------------------------------------
__global__ void k_transpose(const float* __restrict__ in, float* __restrict__ out,
                            int D1, int D2) {
    __shared__ float tile[32][33];
    int b  = blockIdx.z;
    int i0 = blockIdx.y * 32;
    int j0 = blockIdx.x * 32;
    int tx = threadIdx.x, ty = threadIdx.y;
    const float* ip = in  + (size_t)b * D1 * D2;
    float*       op = out + (size_t)b * D1 * D2;
#pragma unroll
    for (int s = 0; s < 32; s += 8)
        tile[ty + s][tx] = ip[(size_t)(i0 + ty + s) * D2 + j0 + tx];
    __syncthreads();
#pragma unroll
    for (int s = 0; s < 32; s += 8)
        op[(size_t)(j0 + ty + s) * D1 + i0 + tx] = tile[tx][ty + s];
}

// ---------------- causal depthwise conv(4) + silu ----------------------------
__global__ void k_conv_silu(const __half* __restrict__ xz,
                            const float* __restrict__ cw,
                            const float* __restrict__ cb,
                            float* __restrict__ u) {
    int i = blockIdx.x * blockDim.x + threadIdx.x;
    if (i >= BL * DI) return;
    int d    = i & (DI - 1);
    int lrow = i >> 9;
    int l    = lrow & (LSEQ - 1);
    float acc = cb[d];
#pragma unroll
    for (int k = 0; k < 4; k++) {
        int ll = l - 3 + k;
        if (ll >= 0)
            acc += cw[d * 4 + k] * __half2float(xz[(size_t)(lrow - 3 + k) * XZW + d]);
    }
    u[i] = acc / (1.f + __expf(-acc));
}

// ---------------- dt ----------------------------------------------------------
__global__ void __launch_bounds__(256) k_dt(
    const float* __restrict__ proj, const float* __restrict__ Wdt,
    const float* __restrict__ bdt, float* __restrict__ dt) {
    __shared__ float sw[DI * RNK];
    __shared__ float sp[16][RNK];
    int tid = threadIdx.x;
    int i0  = blockIdx.x * 16;
    for (int idx = tid; idx < DI * RNK; idx += 256) sw[idx] = Wdt[idx];
    if (tid < 256) {
        int r = tid >> 4, k = tid & 15;
        sp[r][k] = proj[(size_t)(i0 + r) * PROJW + k];
    }
    __syncthreads();
    int d = tid * 2;
    float w0[RNK], w1[RNK];
#pragma unroll
    for (int k = 0; k < RNK; k++) { w0[k] = sw[d * RNK + k]; w1[k] = sw[(d + 1) * RNK + k]; }
    float b0 = bdt[d], b1 = bdt[d + 1];
#pragma unroll 4
    for (int r = 0; r < 16; r++) {
        float s0 = b0, s1 = b1;
#pragma unroll
        for (int k = 0; k < RNK; k++) {
            float pv = sp[r][k];
            s0 += pv * w0[k];
            s1 += pv * w1[k];
        }
        float o0 = fmaxf(s0, 0.f) + log1pf(__expf(-fabsf(s0)));
        float o1 = fmaxf(s1, 0.f) + log1pf(__expf(-fabsf(s1)));
        *(float2*)(dt + (size_t)(i0 + r) * DI + d) = make_float2(o0, o1);
    }
}

// =============== chunked selective scan ======================================
template <int PASS>
__global__ void __launch_bounds__(128) k_scan_chunk(
    const float* __restrict__ dt, const float* __restrict__ u,
    const float* __restrict__ proj, const float* __restrict__ A_log,
    float* __restrict__ Pout, float* __restrict__ heout,
    const float* __restrict__ Hin, float* __restrict__ ys,
    const __half* __restrict__ xz, const float* __restrict__ Dv) {
    __shared__ float sdt[CS * 8], su[CS * 8], sB[CS * 16], sC[CS * 16], sy[CS * 8];
    int blk = blockIdx.x;
    int b   = blk >> 6;
    int d0  = (blk & 63) * 8;
    int chunk = blockIdx.y;
    int tid  = threadIdx.x;
    int dloc = tid >> 4;
    int n    = tid & 15;
    int d    = d0 + dloc;
    float a = -__expf(A_log[d * NST + n]);
    size_t base = (size_t)b * LSEQ + (size_t)chunk * CS;

    for (int idx = tid; idx < CS * 8; idx += 128) {
        int j = idx >> 3, dd = idx & 7;
        size_t g = (base + j) * DI + d0 + dd;
        sdt[idx] = dt[g];
        su[idx]  = u[g];
    }
    for (int idx = tid; idx < CS * 16; idx += 128) {
        int j = idx >> 4, nn = idx & 15;
        size_t g = (base + j) * PROJW;
        sB[idx] = proj[g + 16 + nn];
        if (PASS == 3) sC[idx] = proj[g + 32 + nn];
    }
    __syncthreads();

    size_t sidx = (size_t)chunk * SCANW + (size_t)b * (DI * NST) + d * NST + n;

    if (PASS == 1) {
        float h = 0.f, Pr = 1.f;
#pragma unroll 8
        for (int j = 0; j < CS; j++) {
            float dtv = sdt[j * 8 + dloc];
            float dA  = __expf(dtv * a);
            h  = dA * h + (dtv * su[j * 8 + dloc]) * sB[j * 16 + n];
            Pr *= dA;
        }
        Pout[sidx] = Pr;
        heout[sidx] = h;
    } else {
        float h = Hin[sidx];
#pragma unroll 4
        for (int j = 0; j < CS; j++) {
            float dtv = sdt[j * 8 + dloc];
            float dA  = __expf(dtv * a);
            h = dA * h + (dtv * su[j * 8 + dloc]) * sB[j * 16 + n];
            float yv = h * sC[j * 16 + n];
            yv += __shfl_xor_sync(~0u, yv, 8);
            yv += __shfl_xor_sync(~0u, yv, 4);
            yv += __shfl_xor_sync(~0u, yv, 2);
            yv += __shfl_xor_sync(~0u, yv, 1);
            if (n == 0) sy[j * 8 + dloc] = yv;
        }
        __syncthreads();
        for (int idx = tid; idx < CS * 8; idx += 128) {
            int j = idx >> 3, dd = idx & 7;
            int dg = d0 + dd;
            float zv  = __half2float(xz[(base + j) * XZW + DI + dg]);
            float sil = zv / (1.f + __expf(-zv));
            ys[(base + j) * DI + dg] = (sy[idx] + su[idx] * Dv[dg]) * sil;
        }
    }
}

__global__ void k_scan_carry(const float* __restrict__ P,
                             const float* __restrict__ he,
                             float* __restrict__ H) {
    int tid = blockIdx.x * blockDim.x + threadIdx.x;
    if (tid >= SCANW) return;
    float Hc = 0.f;
#pragma unroll 8
    for (int c = 0; c < NCHUNK; c++) {
        size_t idx = (size_t)c * SCANW + tid;
        H[idx] = Hc;
        Hc = P[idx] * Hc + he[idx];
    }
}

// ================= FP16 tensor-core GEMM =====================================
__device__ __forceinline__ void mma_f16(float& c0, float& c1, float& c2, float& c3,
                                        uint32_t a0, uint32_t a1, uint32_t a2, uint32_t a3,
                                        uint32_t b0, uint32_t b1) {
    asm volatile(
        "mma.sync.aligned.m16n8k16.row.col.f32.f16.f16.f32 "
        "{%0,%1,%2,%3}, {%4,%5,%6,%7}, {%8,%9}, {%0,%1,%2,%3};"
        : "+f"(c0), "+f"(c1), "+f"(c2), "+f"(c3)
        : "r"(a0), "r"(a1), "r"(a2), "r"(a3), "r"(b0), "r"(b1));
}

__device__ __forceinline__ void ldsm4(uint32_t* r, uint32_t addr) {
    asm volatile("ldmatrix.sync.aligned.m8n8.x4.shared.b16 {%0,%1,%2,%3}, [%4];"
                 : "=r"(r[0]), "=r"(r[1]), "=r"(r[2]), "=r"(r[3]) : "r"(addr));
}

__device__ __forceinline__ uint4 pack8(float4 a, float4 b) {
    __half2 h0 = __floats2half2_rn(a.x, a.y);
    __half2 h1 = __floats2half2_rn(a.z, a.w);
    __half2 h2 = __floats2half2_rn(b.x, b.y);
    __half2 h3 = __floats2half2_rn(b.z, b.w);
    uint4 r;
    r.x = *(uint32_t*)&h0; r.y = *(uint32_t*)&h1;
    r.z = *(uint32_t*)&h2; r.w = *(uint32_t*)&h3;
    return r;
}

// C(M,N) = A(M,K) @ Bw(N,K)^T (+ epilogue). Row stride 40 halves.
// EPI: 0 none; 1 bias+gelu; 2 +resid; 3 bias+resid
template <int EPI, int TN, bool AH16, bool OH16>
__global__ void __launch_bounds__(256) k_hgemm(
    const void* __restrict__ Av, const float* __restrict__ Bw,
    const float* __restrict__ bias, const float* __restrict__ resid,
    void* __restrict__ Cv, int M, int N, int K) {
    constexpr int WN   = TN / 4;
    constexpr int NI   = WN / 8;
    constexpr int NP   = NI / 2;
    constexpr int AHW  = 128 * 40;
    constexpr int BHH  = TN * 40;
    constexpr int BUFH = AHW + BHH;

    __shared__ __half sm[2 * BUFH];

    int tid  = threadIdx.x;
    int lane = tid & 31;
    int wid  = tid >> 5;
    int wm   = wid & 1;
    int wn   = wid >> 1;
    int grp  = lane >> 2;
    int l4   = lane & 3;
    int m8   = lane >> 3;
    int lr8  = lane & 7;

    int row0 = blockIdx.y * 128;
    int col0 = blockIdx.x * TN;

    int ar = tid >> 1, ah = (tid & 1) * 16;
    int br, bh;
    if (TN == 128) { br = tid >> 1; bh = (tid & 1) * 16; }
    else           { br = tid >> 2; bh = (tid & 3) * 8;  }

    uint32_t a_base[4], b_base[NP];
#pragma unroll
    for (int mi = 0; mi < 4; mi++)
        a_base[mi] = (uint32_t)__cvta_generic_to_shared(
            &sm[(wm * 64 + mi * 16 + lr8 + 8 * (m8 & 1)) * 40 + (m8 >> 1) * 8]);
#pragma unroll
    for (int p = 0; p < NP; p++)
        b_base[p] = (uint32_t)__cvta_generic_to_shared(
            &sm[AHW + (wn * WN + p * 16 + (m8 >> 1) * 8 + lr8) * 40 + (m8 & 1) * 8]);

    const uint32_t bufB = BUFH * 2;

    float acc[4][NI][4];
#pragma unroll
    for (int mi = 0; mi < 4; mi++)
#pragma unroll
        for (int ni = 0; ni < NI; ni++)
#pragma unroll
            for (int t = 0; t < 4; t++) acc[mi][ni][t] = 0.f;

    const float*  Af = (const float*)Av;
    const __half* Ah = (const __half*)Av;

    float4 ra[4], rb[4];
    uint4  rah[2];

    if (AH16) {
        rah[0] = *(const uint4*)(Ah + (size_t)(row0 + ar) * K + ah);
        rah[1] = *(const uint4*)(Ah + (size_t)(row0 + ar) * K + ah + 8);
    } else {
#pragma unroll
        for (int f = 0; f < 4; f++)
            ra[f] = *(const float4*)(Af + (size_t)(row0 + ar) * K + ah + f * 4);
    }
    if (TN == 128) {
#pragma unroll
        for (int f = 0; f < 4; f++)
            rb[f] = *(const float4*)(Bw + (size_t)(col0 + br) * K + bh + f * 4);
    } else {
#pragma unroll
        for (int f = 0; f < 2; f++)
            rb[f] = *(const float4*)(Bw + (size_t)(col0 + br) * K + bh + f * 4);
    }
    if (AH16) {
        *(uint4*)&sm[ar * 40 + ah]     = rah[0];
        *(uint4*)&sm[ar * 40 + ah + 8] = rah[1];
    } else {
        *(uint4*)&sm[ar * 40 + ah]     = pack8(ra[0], ra[1]);
        *(uint4*)&sm[ar * 40 + ah + 8] = pack8(ra[2], ra[3]);
    }
    if (TN == 128) {
        *(uint4*)&sm[AHW + br * 40 + bh]     = pack8(rb[0], rb[1]);
        *(uint4*)&sm[AHW + br * 40 + bh + 8] = pack8(rb[2], rb[3]);
    } else {
        *(uint4*)&sm[AHW + br * 40 + bh] = pack8(rb[0], rb[1]);
    }
    __syncthreads();

    int buf = 0;
    for (int kt = 0; kt < K; kt += 32) {
        bool more = (kt + 32) < K;
        if (more) {
            if (AH16) {
                rah[0] = *(const uint4*)(Ah + (size_t)(row0 + ar) * K + kt + 32 + ah);
                rah[1] = *(const uint4*)(Ah + (size_t)(row0 + ar) * K + kt + 32 + ah + 8);
            } else {
#pragma unroll
                for (int f = 0; f < 4; f++)
                    ra[f] = *(const float4*)(Af + (size_t)(row0 + ar) * K + kt + 32 + ah + f * 4);
            }
            if (TN == 128) {
#pragma unroll
                for (int f = 0; f < 4; f++)
                    rb[f] = *(const float4*)(Bw + (size_t)(col0 + br) * K + kt + 32 + bh + f * 4);
            } else {
#pragma unroll
                for (int f = 0; f < 2; f++)
                    rb[f] = *(const float4*)(Bw + (size_t)(col0 + br) * K + kt + 32 + bh + f * 4);
            }
        }

        uint32_t boff = buf * bufB;
#pragma unroll
        for (int ks = 0; ks < 2; ks++) {
            uint32_t af[4][4], bfr[NI][2];
#pragma unroll
            for (int mi = 0; mi < 4; mi++)
                ldsm4(af[mi], a_base[mi] + boff + ks * 32);
#pragma unroll
            for (int p = 0; p < NP; p++) {
                uint32_t bq[4];
                ldsm4(bq, b_base[p] + boff + ks * 32);
                bfr[2 * p][0]     = bq[0];
                bfr[2 * p][1]     = bq[1];
                bfr[2 * p + 1][0] = bq[2];
                bfr[2 * p + 1][1] = bq[3];
            }
#pragma unroll
            for (int mi = 0; mi < 4; mi++)
#pragma unroll
                for (int ni = 0; ni < NI; ni++)
                    mma_f16(acc[mi][ni][0], acc[mi][ni][1], acc[mi][ni][2], acc[mi][ni][3],
                            af[mi][0], af[mi][1], af[mi][2], af[mi][3],
                            bfr[ni][0], bfr[ni][1]);
        }

        if (more) {
            uint32_t w = (buf ^ 1) * BUFH;
            if (AH16) {
                *(uint4*)&sm[w + ar * 40 + ah]     = rah[0];
                *(uint4*)&sm[w + ar * 40 + ah + 8] = rah[1];
            } else {
                *(uint4*)&sm[w + ar * 40 + ah]     = pack8(ra[0], ra[1]);
                *(uint4*)&sm[w + ar * 40 + ah + 8] = pack8(ra[2], ra[3]);
            }
            if (TN == 128) {
                *(uint4*)&sm[w + AHW + br * 40 + bh]     = pack8(rb[0], rb[1]);
                *(uint4*)&sm[w + AHW + br * 40 + bh + 8] = pack8(rb[2], rb[3]);
            } else {
                *(uint4*)&sm[w + AHW + br * 40 + bh] = pack8(rb[0], rb[1]);
            }
        }
        __syncthreads();
        buf ^= 1;
    }

    float*  Cf = (float*)Cv;
    __half* Ch = (__half*)Cv;

#pragma unroll
    for (int mi = 0; mi < 4; mi++) {
#pragma unroll
        for (int ni = 0; ni < NI; ni++) {
            int r = row0 + wm * 64 + mi * 16 + grp;
            int c = col0 + wn * WN + ni * 8 + l4 * 2;
#pragma unroll
            for (int half = 0; half < 2; half++) {
                int rr = r + half * 8;
                float v0 = acc[mi][ni][half * 2 + 0];
                float v1 = acc[mi][ni][half * 2 + 1];
                if (EPI == 1) {
                    v0 += bias[c];     v1 += bias[c + 1];
                    v0 = 0.5f * v0 * (1.f + erff(v0 * 0.70710678118654752f));
                    v1 = 0.5f * v1 * (1.f + erff(v1 * 0.70710678118654752f));
                } else if (EPI == 2) {
                    const float2 rv = *(const float2*)(resid + (size_t)rr * N + c);
                    v0 += rv.x; v1 += rv.y;
                } else if (EPI == 3) {
                    const float2 rv = *(const float2*)(resid + (size_t)rr * N + c);
                    v0 += bias[c] + rv.x; v1 += bias[c + 1] + rv.y;
                }
                if (OH16) {
                    __half2 hv = __floats2half2_rn(v0, v1);
                    *(__half2*)(Ch + (size_t)rr * N + c) = hv;
                } else {
                    *(float2*)(Cf + (size_t)rr * N + c) = make_float2(v0, v1);
                }
            }
        }
    }
}

// ---------------- launcher ---------------------------------------------------
extern "C" void kernel_launch(void* const* d_in, const int* in_sizes, int n_in,
                              void* d_out, int out_size) {
    const float* x      = (const float*)d_in[0];
    const float* gamma  = (const float*)d_in[1];
    const float* beta   = (const float*)d_in[2];
    const float* W_in   = (const float*)d_in[3];
    const float* conv_w = (const float*)d_in[4];
    const float* conv_b = (const float*)d_in[5];
    const float* W_xp   = (const float*)d_in[6];
    const float* W_dt   = (const float*)d_in[7];
    const float* b_dt   = (const float*)d_in[8];
    const float* A_log  = (const float*)d_in[9];
    const float* Dv     = (const float*)d_in[10];
    const float* W_out  = (const float*)d_in[11];
    const float* W1     = (const float*)d_in[12];
    const float* b1     = (const float*)d_in[13];
    const float* W2     = (const float*)d_in[14];
    const float* b2     = (const float*)d_in[15];
    float* out = (float*)d_out;

    float *yn, *u, *proj, *wxp, *dt, *ym, *y2, *y3, *Pb, *he, *Hb;
    __half *xz, *hid;
    cudaGetSymbolAddress((void**)&yn,  g_yn);
    cudaGetSymbolAddress((void**)&xz,  g_xz);
    cudaGetSymbolAddress((void**)&u,   g_u);
    cudaGetSymbolAddress((void**)&proj,g_proj);
    cudaGetSymbolAddress((void**)&wxp, g_wxp);
    cudaGetSymbolAddress((void**)&dt,  g_dt);
    cudaGetSymbolAddress((void**)&ym,  g_ym);
    cudaGetSymbolAddress((void**)&y2,  g_y2);
    cudaGetSymbolAddress((void**)&hid, g_hid);
    cudaGetSymbolAddress((void**)&y3,  g_y3);
    cudaGetSymbolAddress((void**)&Pb,  g_P);
    cudaGetSymbolAddress((void**)&he,  g_he);
    cudaGetSymbolAddress((void**)&Hb,  g_H);

    // 0) pad W_xp into 64-row scratch
    k_padw<<<(PROJW * DI) / 256, 256>>>(W_xp, wxp);
    // 1) fused transpose + layernorm -> yn
    {
        dim3 grid(LSEQ / 32, BATCH);
        k_transpose_ln<<<grid, 256>>>(x, gamma, beta, yn);
    }
    // 2) xz = yn @ W_in^T (fp16 out)
    {
        dim3 grid(XZW / 128, BL / 128);
        k_hgemm<0, 128, false, true><<<grid, 256>>>(yn, W_in, nullptr, nullptr, xz, BL, XZW, DIM);
    }
    // 3) conv + silu -> u
    k_conv_silu<<<(BL * DI) / 256, 256>>>(xz, conv_w, conv_b, u);
    // 4) proj = u @ wxp^T (GEMM, N=64 padded)
    {
        dim3 grid(1, BL / 128);
        k_hgemm<0, 64, false, false><<<grid, 256>>>(u, wxp, nullptr, nullptr, proj, BL, PROJW, DI);
    }
    // 5) dt
    k_dt<<<BL / 16, 256>>>(proj, W_dt, b_dt, dt);
    // 6) chunked selective scan (+fused gate) -> ym
    {
        dim3 grid(BATCH * (DI / 8), NCHUNK);
        k_scan_chunk<1><<<grid, 128>>>(dt, u, proj, A_log, Pb, he, nullptr, nullptr, nullptr, nullptr);
        k_scan_carry<<<SCANW / 256, 256>>>(Pb, he, Hb);
        k_scan_chunk<3><<<grid, 128>>>(dt, u, proj, A_log, nullptr, nullptr, Hb, ym, xz, Dv);
    }
    // 7) y2 = ym @ W_out^T + yn
    {
        dim3 grid(DIM / 64, BL / 128);
        k_hgemm<2, 64, false, false><<<grid, 256>>>(ym, W_out, nullptr, yn, y2, BL, DIM, DI);
    }
    // 8) hid = gelu(y2 @ W1^T + b1) (fp16 out)
    {
        dim3 grid(HIDW / 128, BL / 128);
        k_hgemm<1, 128, false, true><<<grid, 256>>>(y2, W1, b1, nullptr, hid, BL, HIDW, DIM);
    }
    // 9) y3 = hid @ W2^T + b2 + y2 (fp16 A)
    {
        dim3 grid(DIM / 64, BL / 128);
        k_hgemm<3, 64, true, false><<<grid, 256>>>(hid, W2, b2, y2, y3, BL, DIM, HIDW);
    }
    // 10) transpose y3 (B,L,C) -> out (B,C,L)
    {
        dim3 tb(32, 8);
        dim3 grid(DIM / 32, LSEQ / 32, BATCH);
        k_transpose<<<grid, tb>>>(y3, out, LSEQ, DIM);
    }
}